// round 6
// baseline (speedup 1.0000x reference)
#include <cuda_runtime.h>
#include <cuda_bf16.h>
#include <math.h>
#include <stdint.h>

#define S_LEN 3136
#define E_DIM 1024
#define H_NUM 16
#define D_DIM 64
#define NTILES 25   // ceil(3136/128)

typedef __nv_bfloat16 bf16;

// ---------------------------------------------------------------------------
// Device scratch (allocation is forbidden)
// ---------------------------------------------------------------------------
__device__ float g_qkv[3][H_NUM * S_LEN * D_DIM];   // fp32 head-major q,k,v

__device__ __align__(16) bf16 g_Hhi[S_LEN * E_DIM];
__device__ __align__(16) bf16 g_Hlo[S_LEN * E_DIM];
__device__ __align__(16) bf16 g_Whi[4][E_DIM * E_DIM];
__device__ __align__(16) bf16 g_Wlo[4][E_DIM * E_DIM];
__device__ __align__(16) bf16 g_Qhi[H_NUM * S_LEN * D_DIM];
__device__ __align__(16) bf16 g_Qlo[H_NUM * S_LEN * D_DIM];
__device__ __align__(16) bf16 g_Khi[H_NUM * S_LEN * D_DIM];
__device__ __align__(16) bf16 g_Klo[H_NUM * S_LEN * D_DIM];
__device__ __align__(16) bf16 g_Vthi[H_NUM * D_DIM * S_LEN];   // [h][d][s]
__device__ __align__(16) bf16 g_Vtlo[H_NUM * D_DIM * S_LEN];
__device__ __align__(16) bf16 g_Ehi[(long)H_NUM * S_LEN * S_LEN];  // unnormalized exp
__device__ __align__(16) bf16 g_Elo[(long)H_NUM * S_LEN * S_LEN];
__device__ __align__(16) bf16 g_AOhi[S_LEN * E_DIM];
__device__ __align__(16) bf16 g_AOlo[S_LEN * E_DIM];
__device__ float g_part[NTILES * H_NUM * S_LEN];   // per-(ntile,row) partial sums
__device__ float g_isum[H_NUM * S_LEN];            // 1 / rowsum

// ---------------------------------------------------------------------------
// PTX helpers (sm_80-era: cp.async + ldmatrix + mma.sync)
// ---------------------------------------------------------------------------
__device__ __forceinline__ uint32_t smem_u32(const void* p) {
    uint32_t a;
    asm("{ .reg .u64 t; cvta.to.shared.u64 t, %1; cvt.u32.u64 %0, t; }" : "=r"(a) : "l"(p));
    return a;
}
__device__ __forceinline__ void cp16(uint32_t dst, const void* src, int srcsize) {
    asm volatile("cp.async.cg.shared.global [%0], [%1], 16, %2;"
                 :: "r"(dst), "l"(src), "r"(srcsize));
}
__device__ __forceinline__ void cpcommit() { asm volatile("cp.async.commit_group;"); }
template <int N> __device__ __forceinline__ void cpwait() {
    asm volatile("cp.async.wait_group %0;" :: "n"(N));
}
__device__ __forceinline__ void ldm4(uint32_t* r, uint32_t a) {
    asm volatile("ldmatrix.sync.aligned.m8n8.x4.shared.b16 {%0,%1,%2,%3}, [%4];"
                 : "=r"(r[0]), "=r"(r[1]), "=r"(r[2]), "=r"(r[3]) : "r"(a));
}
__device__ __forceinline__ void ldm2(uint32_t* r, uint32_t a) {
    asm volatile("ldmatrix.sync.aligned.m8n8.x2.shared.b16 {%0,%1}, [%2];"
                 : "=r"(r[0]), "=r"(r[1]) : "r"(a));
}
__device__ __forceinline__ void mma16816(float* d, const uint32_t* a, const uint32_t* b) {
    asm volatile("mma.sync.aligned.m16n8k16.row.col.f32.bf16.bf16.f32 "
                 "{%0,%1,%2,%3}, {%4,%5,%6,%7}, {%8,%9}, {%0,%1,%2,%3};"
                 : "+f"(d[0]), "+f"(d[1]), "+f"(d[2]), "+f"(d[3])
                 : "r"(a[0]), "r"(a[1]), "r"(a[2]), "r"(a[3]), "r"(b[0]), "r"(b[1]));
}
__device__ __forceinline__ void st_split2(bf16* hi, bf16* lo, float a, float b) {
    __nv_bfloat162 h;
    h.x = __float2bfloat16(a);
    h.y = __float2bfloat16(b);
    *(__nv_bfloat162*)hi = h;
    __nv_bfloat162 l;
    l.x = __float2bfloat16(a - __bfloat162float(h.x));
    l.y = __float2bfloat16(b - __bfloat162float(h.y));
    *(__nv_bfloat162*)lo = l;
}

// ---------------------------------------------------------------------------
// bf16x3 TN GEMM via mma.sync, 2-stage cp.async double buffer (R3-proven core)
//   A: bf16 hi/lo rows [M, K-contig] stride aRow;  B: bf16 hi/lo rows [N, K-contig]
// EPI 0: fp32 C[z*cBatch + m*ldc + n]
// EPI 1: fp32 head-major qkv: C[(z*H + (n>>6))*S*64 + m*64 + (n&63)]
// EPI 2: PV: AO bf16 split at [m*E + z*64 + n], scaled by invsum[z*S+m].
//        ALSO: in the mainloop, each A(=E) tile is normalized ((hi+lo)*invsum)
//        and streamed to fp32 attn_weights C[z*cBatch + m*ldc + k] (grid.x==1,
//        so each E element passes through smem exactly once).
// EPI 3: score: e=exp(v); bf16 split E at [z*S*S + m*S + n]; partial row sums
//        via shfl reduction (few shared atomics)
// ---------------------------------------------------------------------------
template <int N_TILE, int EPI>
__global__ void __launch_bounds__(256, 1) mma_gemm(
    const bf16* __restrict__ Ahi, const bf16* __restrict__ Alo, long aRow, long aBatch,
    const bf16* __restrict__ Bhi, const bf16* __restrict__ Blo, long bRow, long bBatch,
    float* __restrict__ C, long ldc, long cBatch,
    bf16* __restrict__ Dhi, bf16* __restrict__ Dlo,
    const float* __restrict__ invsum, float* __restrict__ part,
    int kChunks, int M_valid, int N_valid) {

    constexpr int AST = 80;                 // smem bytes per 32-bf16 row (64 + 16 pad)
    constexpr int A_BYTES = 128 * AST;
    constexpr int B_BYTES = N_TILE * AST;
    constexpr int STAGE = 2 * A_BYTES + 2 * B_BYTES;

    extern __shared__ char smem[];
    const uint32_t sb = smem_u32(smem);
    __shared__ float s_red[128];

    const int tid = threadIdx.x;
    const int wid = tid >> 5, lane = tid & 31;
    constexpr int WC = (N_TILE == 128) ? 4 : 2;
    constexpr int WM = (N_TILE == 128) ? 64 : 32;
    constexpr int WN = 32;
    constexpr int MI = WM / 16, NI = WN / 8;
    const int warpM = (wid / WC) * WM;
    const int warpN = (wid % WC) * WN;

    const int mBase = blockIdx.y * 128;
    const int nBase = blockIdx.x * N_TILE;
    const int z = blockIdx.z;
    Ahi += aBatch * z; Alo += aBatch * z;
    Bhi += bBatch * z; Blo += bBatch * z;

    float acc[MI][NI][4];
#pragma unroll
    for (int i = 0; i < MI; i++)
#pragma unroll
        for (int j = 0; j < NI; j++)
#pragma unroll
            for (int q = 0; q < 4; q++) acc[i][j][q] = 0.0f;

    if (EPI == 3) {
        if (tid < 128) s_red[tid] = 0.0f;
    }

    // EPI 2: per-thread fixed row assignment for the fused normalize-write
    const int nm_r   = tid >> 1;             // 0..127
    const int nm_row = mBase + nm_r;
    const int nm_half = tid & 1;             // which 16-col half of the 32-col chunk
    float nm_inv = 0.0f;
    if (EPI == 2 && nm_row < M_valid) nm_inv = invsum[(long)z * S_LEN + nm_row];

    auto issue_loads = [&](int c) {
        const long k0 = (long)c * 32;
        const uint32_t st = sb + (c & 1) * STAGE;
        for (int i = tid; i < 512; i += 256) {
            const int r = i >> 2, u = i & 3;
            const int row = mBase + r;
            const int ok = (row < M_valid) ? 16 : 0;
            const long srow = (row < M_valid) ? row : (M_valid - 1);
            const long off = srow * aRow + k0 + u * 8;
            const uint32_t dst = st + r * AST + u * 16;
            cp16(dst, Ahi + off, ok);
            cp16(dst + A_BYTES, Alo + off, ok);
        }
        for (int i = tid; i < N_TILE * 4; i += 256) {
            const int r = i >> 2, u = i & 3;
            const int row = nBase + r;
            const int ok = (row < N_valid) ? 16 : 0;
            const long srow = (row < N_valid) ? row : (N_valid - 1);
            const long off = srow * bRow + k0 + u * 8;
            const uint32_t dst = st + 2 * A_BYTES + r * AST + u * 16;
            cp16(dst, Bhi + off, ok);
            cp16(dst + B_BYTES, Blo + off, ok);
        }
        cpcommit();
    };

    issue_loads(0);

    for (int c = 0; c < kChunks; c++) {
        if (c + 1 < kChunks) { issue_loads(c + 1); cpwait<1>(); }
        else                 { cpwait<0>(); }
        __syncthreads();

        const uint32_t st = sb + (c & 1) * STAGE;
        const uint32_t aH = st, aL = st + A_BYTES;
        const uint32_t bH = st + 2 * A_BYTES, bL = bH + B_BYTES;

        // ---- EPI 2: fused normalize: attn_w = (Ehi + Elo) * invsum ----
        if (EPI == 2) {
            if (nm_row < M_valid) {
                const size_t so = (size_t)(c & 1) * STAGE + (size_t)nm_r * AST + nm_half * 32;
                const uint4 h0 = *(const uint4*)(smem + so);
                const uint4 h1 = *(const uint4*)(smem + so + 16);
                const uint4 l0 = *(const uint4*)(smem + so + A_BYTES);
                const uint4 l1 = *(const uint4*)(smem + so + A_BYTES + 16);
                const uint32_t hh[8] = {h0.x, h0.y, h0.z, h0.w, h1.x, h1.y, h1.z, h1.w};
                const uint32_t ll[8] = {l0.x, l0.y, l0.z, l0.w, l1.x, l1.y, l1.z, l1.w};
                float o[16];
#pragma unroll
                for (int j = 0; j < 8; j++) {
                    __nv_bfloat162 hb = *(const __nv_bfloat162*)&hh[j];
                    __nv_bfloat162 lb = *(const __nv_bfloat162*)&ll[j];
                    o[j * 2 + 0] = (__bfloat162float(hb.x) + __bfloat162float(lb.x)) * nm_inv;
                    o[j * 2 + 1] = (__bfloat162float(hb.y) + __bfloat162float(lb.y)) * nm_inv;
                }
                float* wp = C + (long)z * cBatch + (long)nm_row * ldc + (long)c * 32 + nm_half * 16;
                *(float4*)(wp + 0)  = make_float4(o[0],  o[1],  o[2],  o[3]);
                *(float4*)(wp + 4)  = make_float4(o[4],  o[5],  o[6],  o[7]);
                *(float4*)(wp + 8)  = make_float4(o[8],  o[9],  o[10], o[11]);
                *(float4*)(wp + 12) = make_float4(o[12], o[13], o[14], o[15]);
            }
        }

#pragma unroll
        for (int s = 0; s < 2; s++) {
            uint32_t aHf[MI][4], aLf[MI][4], bHf[NI][2], bLf[NI][2];
            const int arow = warpM + (lane & 15);
            const uint32_t acol = s * 32 + (lane >> 4) * 16;
#pragma unroll
            for (int mi = 0; mi < MI; mi++) {
                const uint32_t ao = (uint32_t)((arow + mi * 16) * AST) + acol;
                ldm4(aHf[mi], aH + ao);
                ldm4(aLf[mi], aL + ao);
            }
            const int l16 = lane & 15;
            const int brow = warpN + (l16 & 7);
            const uint32_t bcol = s * 32 + (l16 >> 3) * 16;
#pragma unroll
            for (int ni = 0; ni < NI; ni++) {
                const uint32_t bo = (uint32_t)((brow + ni * 8) * AST) + bcol;
                ldm2(bHf[ni], bH + bo);
                ldm2(bLf[ni], bL + bo);
            }
#pragma unroll
            for (int mi = 0; mi < MI; mi++)
#pragma unroll
                for (int ni = 0; ni < NI; ni++) {
                    mma16816(acc[mi][ni], aHf[mi], bHf[ni]);
                    mma16816(acc[mi][ni], aHf[mi], bLf[ni]);
                    mma16816(acc[mi][ni], aLf[mi], bHf[ni]);
                }
        }
        __syncthreads();
    }

    // ---------------- epilogue ----------------
    if (EPI == 3) {
        // exp + store E splits + row partial sums (shfl-reduced)
#pragma unroll
        for (int mi = 0; mi < MI; mi++) {
#pragma unroll
            for (int h = 0; h < 2; h++) {
                const int rl = warpM + mi * 16 + (lane >> 2) + h * 8;
                const int row = mBase + rl;
                const bool rok = (row < M_valid);
                float rsum = 0.0f;
#pragma unroll
                for (int ni = 0; ni < NI; ni++) {
                    const int col0 = nBase + warpN + ni * 8 + (lane & 3) * 2;
                    float e0 = 0.f, e1 = 0.f;
                    if (rok && col0 < N_valid) {
                        e0 = __expf(acc[mi][ni][h * 2 + 0]);
                        e1 = __expf(acc[mi][ni][h * 2 + 1]);
                        const long o = (long)z * S_LEN * S_LEN + (long)row * S_LEN + col0;
                        st_split2(Dhi + o, Dlo + o, e0, e1);
                    }
                    rsum += e0 + e1;
                }
                rsum += __shfl_xor_sync(0xFFFFFFFFu, rsum, 1);
                rsum += __shfl_xor_sync(0xFFFFFFFFu, rsum, 2);
                if ((lane & 3) == 0 && rok) atomicAdd(&s_red[rl], rsum);
            }
        }
        __syncthreads();
        if (tid < 128) {
            const int row = mBase + tid;
            if (row < M_valid)
                part[(long)blockIdx.x * (H_NUM * S_LEN) + (long)z * S_LEN + row] = s_red[tid];
        }
        return;
    }

#pragma unroll
    for (int mi = 0; mi < MI; mi++) {
#pragma unroll
        for (int ni = 0; ni < NI; ni++) {
            const int rl0 = warpM + mi * 16 + (lane >> 2);
            const int col0 = nBase + warpN + ni * 8 + (lane & 3) * 2;
#pragma unroll
            for (int h = 0; h < 2; h++) {
                const int row = mBase + rl0 + h * 8;
                if (row >= M_valid) continue;
                const float v0 = acc[mi][ni][h * 2 + 0];
                const float v1 = acc[mi][ni][h * 2 + 1];
                if (EPI == 0) {
                    if (col0 < N_valid) {
                        C[(long)z * cBatch + (long)row * ldc + col0] = v0;
                        C[(long)z * cBatch + (long)row * ldc + col0 + 1] = v1;
                    }
                } else if (EPI == 1) {
                    const long o0 = ((long)z * H_NUM + (col0 >> 6)) * S_LEN * 64 + (long)row * 64 + (col0 & 63);
                    C[o0] = v0;
                    C[o0 + 1] = v1;
                } else if (EPI == 2) {
                    const float sc = invsum[(long)z * S_LEN + row];
                    const long o = (long)row * E_DIM + (long)z * 64 + col0;
                    st_split2(Dhi + o, Dlo + o, v0 * sc, v1 * sc);
                }
            }
        }
    }
}

// ---------------------------------------------------------------------------
// Small kernels
// ---------------------------------------------------------------------------
__global__ void split_kernel(const float* __restrict__ src, bf16* __restrict__ hi,
                             bf16* __restrict__ lo, long n) {
    long i = ((long)blockIdx.x * blockDim.x + threadIdx.x) * 4;
    if (i >= n) return;
    float4 v = *(const float4*)(src + i);
    float f[4] = {v.x, v.y, v.z, v.w};
#pragma unroll
    for (int j = 0; j < 4; j++) {
        bf16 h = __float2bfloat16(f[j]);
        hi[i + j] = h;
        lo[i + j] = __float2bfloat16(f[j] - __bfloat162float(h));
    }
}

__global__ void rope_split_kernel(const float* __restrict__ Q, const float* __restrict__ K,
                                  const float* __restrict__ cosp, const float* __restrict__ sinp) {
    const long total = (long)H_NUM * S_LEN * 32;
    long idx = (long)blockIdx.x * blockDim.x + threadIdx.x;
    if (idx >= total) return;
    const int d = (int)(idx & 31);
    const long hs = idx >> 5;
    const int s = (int)(hs % S_LEN);
    const long base = hs << 6;

    const float c1 = cosp[s * 64 + d], s1 = sinp[s * 64 + d];
    const float c2 = cosp[s * 64 + d + 32], s2 = sinp[s * 64 + d + 32];

    float q1 = Q[base + d], q2 = Q[base + d + 32];
    float qa = (q1 * c1 - q2 * s1) * 0.125f;
    float qb = (q2 * c2 + q1 * s2) * 0.125f;
    float k1 = K[base + d], k2 = K[base + d + 32];
    float ka = k1 * c1 - k2 * s1;
    float kb = k2 * c2 + k1 * s2;

    bf16 h;
    h = __float2bfloat16(qa); g_Qhi[base + d] = h; g_Qlo[base + d] = __float2bfloat16(qa - __bfloat162float(h));
    h = __float2bfloat16(qb); g_Qhi[base + d + 32] = h; g_Qlo[base + d + 32] = __float2bfloat16(qb - __bfloat162float(h));
    h = __float2bfloat16(ka); g_Khi[base + d] = h; g_Klo[base + d] = __float2bfloat16(ka - __bfloat162float(h));
    h = __float2bfloat16(kb); g_Khi[base + d + 32] = h; g_Klo[base + d + 32] = __float2bfloat16(kb - __bfloat162float(h));
}

__global__ void vtrans_kernel(const float* __restrict__ V) {
    __shared__ float tile[64][65];
    const int h = blockIdx.z;
    const int s0 = blockIdx.x * 64;
    const int t = threadIdx.x;
    for (int i = t; i < 4096; i += 256) {
        int s = i >> 6, d = i & 63;
        tile[s][d] = V[((long)h * S_LEN + s0 + s) * 64 + d];
    }
    __syncthreads();
    for (int i = t; i < 4096; i += 256) {
        int d = i >> 6, s = i & 63;
        float v = tile[s][d];
        bf16 hi = __float2bfloat16(v);
        long o = ((long)h * 64 + d) * S_LEN + s0 + s;
        g_Vthi[o] = hi;
        g_Vtlo[o] = __float2bfloat16(v - __bfloat162float(hi));
    }
}

__global__ void reduce_rowsum_kernel() {
    int i = blockIdx.x * blockDim.x + threadIdx.x;
    if (i >= H_NUM * S_LEN) return;
    float s = 0.f;
#pragma unroll
    for (int t = 0; t < NTILES; t++) s += g_part[t * (H_NUM * S_LEN) + i];
    g_isum[i] = 1.0f / s;
}

// ---------------------------------------------------------------------------
// Launch
// ---------------------------------------------------------------------------
extern "C" void kernel_launch(void* const* d_in, const int* in_sizes, int n_in,
                              void* d_out, int out_size) {
    const float* hidden = (const float*)d_in[0];
    const float* cosp   = (const float*)d_in[1];
    const float* sinp   = (const float*)d_in[2];
    const float* w[4]   = {(const float*)d_in[3], (const float*)d_in[4],
                           (const float*)d_in[5], (const float*)d_in[6]};

    float* out    = (float*)d_out;
    float* attn_w = out + (long)S_LEN * E_DIM;

    float* qkv; cudaGetSymbolAddress((void**)&qkv, g_qkv);
    bf16 *Hhi, *Hlo, *Whi, *Wlo, *Qhi, *Qlo, *Khi, *Klo, *Vthi, *Vtlo, *Ehi, *Elo, *AOhi, *AOlo;
    float *part, *isum;
    cudaGetSymbolAddress((void**)&Hhi, g_Hhi);  cudaGetSymbolAddress((void**)&Hlo, g_Hlo);
    cudaGetSymbolAddress((void**)&Whi, g_Whi);  cudaGetSymbolAddress((void**)&Wlo, g_Wlo);
    cudaGetSymbolAddress((void**)&Qhi, g_Qhi);  cudaGetSymbolAddress((void**)&Qlo, g_Qlo);
    cudaGetSymbolAddress((void**)&Khi, g_Khi);  cudaGetSymbolAddress((void**)&Klo, g_Klo);
    cudaGetSymbolAddress((void**)&Vthi, g_Vthi); cudaGetSymbolAddress((void**)&Vtlo, g_Vtlo);
    cudaGetSymbolAddress((void**)&Ehi, g_Ehi);  cudaGetSymbolAddress((void**)&Elo, g_Elo);
    cudaGetSymbolAddress((void**)&AOhi, g_AOhi); cudaGetSymbolAddress((void**)&AOlo, g_AOlo);
    cudaGetSymbolAddress((void**)&part, g_part); cudaGetSymbolAddress((void**)&isum, g_isum);

    const int SMEM128 = 2 * (2 * 128 * 80 + 2 * 128 * 80);  // 81920
    const int SMEM64  = 2 * (2 * 128 * 80 + 2 * 64 * 80);   // 61440
    cudaFuncSetAttribute(mma_gemm<128, 0>, cudaFuncAttributeMaxDynamicSharedMemorySize, SMEM128);
    cudaFuncSetAttribute(mma_gemm<128, 1>, cudaFuncAttributeMaxDynamicSharedMemorySize, SMEM128);
    cudaFuncSetAttribute(mma_gemm<128, 3>, cudaFuncAttributeMaxDynamicSharedMemorySize, SMEM128);
    cudaFuncSetAttribute(mma_gemm<64, 2>,  cudaFuncAttributeMaxDynamicSharedMemorySize, SMEM64);

    // 1) bf16 splits of hidden + weights
    {
        long n = (long)S_LEN * E_DIM;
        split_kernel<<<(int)((n / 4 + 255) / 256), 256>>>(hidden, Hhi, Hlo, n);
        long nw = (long)E_DIM * E_DIM;
        for (int i = 0; i < 4; i++)
            split_kernel<<<(int)((nw / 4 + 255) / 256), 256>>>(w[i], Whi + (long)i * nw, Wlo + (long)i * nw, nw);
    }

    // 2) QKV projections, batched over z={q,k,v} (head-major fp32)
    {
        dim3 g(E_DIM / 128, (S_LEN + 127) / 128, 3);
        mma_gemm<128, 1><<<g, 256, SMEM128>>>(Hhi, Hlo, E_DIM, 0,
                                              Whi, Wlo, E_DIM, (long)E_DIM * E_DIM,
                                              qkv, 0, 0, nullptr, nullptr, nullptr, nullptr,
                                              32, S_LEN, E_DIM);
    }

    // 3) RoPE + split (1/sqrt(D) folded into Q); V transpose + split
    {
        long total = (long)H_NUM * S_LEN * 32;
        const long HSD = (long)H_NUM * S_LEN * D_DIM;
        rope_split_kernel<<<(int)((total + 255) / 256), 256>>>(qkv, qkv + HSD, cosp, sinp);
        dim3 gv(S_LEN / 64, 1, H_NUM);
        vtrans_kernel<<<gv, 256>>>(qkv + 2 * HSD);
    }

    // 4) score GEMM: E = exp(Q K^T / 8) (bf16 splits) + partial row sums
    {
        dim3 g((S_LEN + 127) / 128, (S_LEN + 127) / 128, H_NUM);
        mma_gemm<128, 3><<<g, 256, SMEM128>>>(Qhi, Qlo, 64, (long)S_LEN * 64,
                                              Khi, Klo, 64, (long)S_LEN * 64,
                                              nullptr, 0, 0, Ehi, Elo, nullptr, part,
                                              2, S_LEN, S_LEN);
    }

    // 5) row sums -> inverse
    reduce_rowsum_kernel<<<(H_NUM * S_LEN + 255) / 256, 256>>>();

    // 6) PV (unnormalized E) -> AO bf16 splits; fused in mainloop:
    //    attn_weights fp32 = (Ehi+Elo)*invsum streamed from the smem A tiles.
    {
        dim3 g(1, (S_LEN + 127) / 128, H_NUM);
        mma_gemm<64, 2><<<g, 256, SMEM64>>>(Ehi, Elo, S_LEN, (long)S_LEN * S_LEN,
                                            Vthi, Vtlo, S_LEN, (long)64 * S_LEN,
                                            attn_w, S_LEN, (long)S_LEN * S_LEN,
                                            AOhi, AOlo, isum, nullptr,
                                            98, S_LEN, 64);
    }

    // 7) out = AO Wo^T
    {
        dim3 g(E_DIM / 128, (S_LEN + 127) / 128, 1);
        long nw = (long)E_DIM * E_DIM;
        mma_gemm<128, 0><<<g, 256, SMEM128>>>(AOhi, AOlo, E_DIM, 0,
                                              Whi + 3 * nw, Wlo + 3 * nw, E_DIM, 0,
                                              out, E_DIM, 0, nullptr, nullptr, nullptr, nullptr,
                                              32, S_LEN, E_DIM);
    }
}

// round 7
// speedup vs baseline: 1.0546x; 1.0546x over previous
#include <cuda_runtime.h>
#include <cuda_bf16.h>
#include <math.h>
#include <stdint.h>

#define S_LEN 3136
#define E_DIM 1024
#define H_NUM 16
#define D_DIM 64
#define NTILES 25   // ceil(3136/128)

typedef __nv_bfloat16 bf16;

// ---------------------------------------------------------------------------
// Device scratch (allocation is forbidden)
// ---------------------------------------------------------------------------
__device__ float g_qkv[3][H_NUM * S_LEN * D_DIM];   // fp32 head-major q,k,v

__device__ __align__(16) bf16 g_Hhi[S_LEN * E_DIM];
__device__ __align__(16) bf16 g_Hlo[S_LEN * E_DIM];
__device__ __align__(16) bf16 g_Whi[4][E_DIM * E_DIM];
__device__ __align__(16) bf16 g_Wlo[4][E_DIM * E_DIM];
__device__ __align__(16) bf16 g_Qhi[H_NUM * S_LEN * D_DIM];
__device__ __align__(16) bf16 g_Qlo[H_NUM * S_LEN * D_DIM];
__device__ __align__(16) bf16 g_Khi[H_NUM * S_LEN * D_DIM];
__device__ __align__(16) bf16 g_Klo[H_NUM * S_LEN * D_DIM];
__device__ __align__(16) bf16 g_Vthi[H_NUM * D_DIM * S_LEN];   // [h][d][s]
__device__ __align__(16) bf16 g_Vtlo[H_NUM * D_DIM * S_LEN];
__device__ __align__(16) bf16 g_Ehi[(long)H_NUM * S_LEN * S_LEN];  // unnormalized exp
__device__ __align__(16) bf16 g_Elo[(long)H_NUM * S_LEN * S_LEN];
__device__ __align__(16) bf16 g_AOhi[S_LEN * E_DIM];
__device__ __align__(16) bf16 g_AOlo[S_LEN * E_DIM];
__device__ float g_part[NTILES * H_NUM * S_LEN];   // per-(ntile,row) partial sums
__device__ float g_isum[H_NUM * S_LEN];            // 1 / rowsum

// ---------------------------------------------------------------------------
// PTX helpers (sm_80-era: cp.async + ldmatrix + mma.sync)
// ---------------------------------------------------------------------------
__device__ __forceinline__ uint32_t smem_u32(const void* p) {
    uint32_t a;
    asm("{ .reg .u64 t; cvta.to.shared.u64 t, %1; cvt.u32.u64 %0, t; }" : "=r"(a) : "l"(p));
    return a;
}
__device__ __forceinline__ void cp16(uint32_t dst, const void* src, int srcsize) {
    asm volatile("cp.async.cg.shared.global [%0], [%1], 16, %2;"
                 :: "r"(dst), "l"(src), "r"(srcsize));
}
__device__ __forceinline__ void cpcommit() { asm volatile("cp.async.commit_group;"); }
template <int N> __device__ __forceinline__ void cpwait() {
    asm volatile("cp.async.wait_group %0;" :: "n"(N));
}
__device__ __forceinline__ void ldm4(uint32_t* r, uint32_t a) {
    asm volatile("ldmatrix.sync.aligned.m8n8.x4.shared.b16 {%0,%1,%2,%3}, [%4];"
                 : "=r"(r[0]), "=r"(r[1]), "=r"(r[2]), "=r"(r[3]) : "r"(a));
}
__device__ __forceinline__ void ldm2(uint32_t* r, uint32_t a) {
    asm volatile("ldmatrix.sync.aligned.m8n8.x2.shared.b16 {%0,%1}, [%2];"
                 : "=r"(r[0]), "=r"(r[1]) : "r"(a));
}
__device__ __forceinline__ void mma16816(float* d, const uint32_t* a, const uint32_t* b) {
    asm volatile("mma.sync.aligned.m16n8k16.row.col.f32.bf16.bf16.f32 "
                 "{%0,%1,%2,%3}, {%4,%5,%6,%7}, {%8,%9}, {%0,%1,%2,%3};"
                 : "+f"(d[0]), "+f"(d[1]), "+f"(d[2]), "+f"(d[3])
                 : "r"(a[0]), "r"(a[1]), "r"(a[2]), "r"(a[3]), "r"(b[0]), "r"(b[1]));
}
__device__ __forceinline__ void st_split2(bf16* hi, bf16* lo, float a, float b) {
    __nv_bfloat162 h;
    h.x = __float2bfloat16(a);
    h.y = __float2bfloat16(b);
    *(__nv_bfloat162*)hi = h;
    __nv_bfloat162 l;
    l.x = __float2bfloat16(a - __bfloat162float(h.x));
    l.y = __float2bfloat16(b - __bfloat162float(h.y));
    *(__nv_bfloat162*)lo = l;
}

// ---------------------------------------------------------------------------
// bf16x3 TN GEMM via mma.sync, 2-stage cp.async double buffer (R5-proven core)
// EPI 0: fp32 C[z*cBatch + m*ldc + n]
// EPI 1: fp32 head-major qkv: C[(z*H + (n>>6))*S*64 + m*64 + (n&63)]
// EPI 2: PV: AO bf16 split at [m*E + z*64 + n], scaled by invsum[z*S+m]
// EPI 3: score: e=exp(v); bf16 split E; shfl-reduced partial row sums
// ---------------------------------------------------------------------------
template <int N_TILE, int EPI>
__global__ void __launch_bounds__(256, 1) mma_gemm(
    const bf16* __restrict__ Ahi, const bf16* __restrict__ Alo, long aRow, long aBatch,
    const bf16* __restrict__ Bhi, const bf16* __restrict__ Blo, long bRow, long bBatch,
    float* __restrict__ C, long ldc, long cBatch,
    bf16* __restrict__ Dhi, bf16* __restrict__ Dlo,
    const float* __restrict__ invsum, float* __restrict__ part,
    int kChunks, int M_valid, int N_valid) {

    constexpr int AST = 80;                 // smem bytes per 32-bf16 row (64 + 16 pad)
    constexpr int A_BYTES = 128 * AST;
    constexpr int B_BYTES = N_TILE * AST;
    constexpr int STAGE = 2 * A_BYTES + 2 * B_BYTES;

    extern __shared__ char smem[];
    const uint32_t sb = smem_u32(smem);
    __shared__ float s_red[128];

    const int tid = threadIdx.x;
    const int wid = tid >> 5, lane = tid & 31;
    constexpr int WC = (N_TILE == 128) ? 4 : 2;
    constexpr int WM = (N_TILE == 128) ? 64 : 32;
    constexpr int WN = 32;
    constexpr int MI = WM / 16, NI = WN / 8;
    const int warpM = (wid / WC) * WM;
    const int warpN = (wid % WC) * WN;

    const int mBase = blockIdx.y * 128;
    const int nBase = blockIdx.x * N_TILE;
    const int z = blockIdx.z;
    Ahi += aBatch * z; Alo += aBatch * z;
    Bhi += bBatch * z; Blo += bBatch * z;

    float acc[MI][NI][4];
#pragma unroll
    for (int i = 0; i < MI; i++)
#pragma unroll
        for (int j = 0; j < NI; j++)
#pragma unroll
            for (int q = 0; q < 4; q++) acc[i][j][q] = 0.0f;

    if (EPI == 3) {
        if (tid < 128) s_red[tid] = 0.0f;
    }

    auto issue_loads = [&](int c) {
        const long k0 = (long)c * 32;
        const uint32_t st = sb + (c & 1) * STAGE;
        for (int i = tid; i < 512; i += 256) {
            const int r = i >> 2, u = i & 3;
            const int row = mBase + r;
            const int ok = (row < M_valid) ? 16 : 0;
            const long srow = (row < M_valid) ? row : (M_valid - 1);
            const long off = srow * aRow + k0 + u * 8;
            const uint32_t dst = st + r * AST + u * 16;
            cp16(dst, Ahi + off, ok);
            cp16(dst + A_BYTES, Alo + off, ok);
        }
        for (int i = tid; i < N_TILE * 4; i += 256) {
            const int r = i >> 2, u = i & 3;
            const int row = nBase + r;
            const int ok = (row < N_valid) ? 16 : 0;
            const long srow = (row < N_valid) ? row : (N_valid - 1);
            const long off = srow * bRow + k0 + u * 8;
            const uint32_t dst = st + 2 * A_BYTES + r * AST + u * 16;
            cp16(dst, Bhi + off, ok);
            cp16(dst + B_BYTES, Blo + off, ok);
        }
        cpcommit();
    };

    issue_loads(0);

    for (int c = 0; c < kChunks; c++) {
        if (c + 1 < kChunks) { issue_loads(c + 1); cpwait<1>(); }
        else                 { cpwait<0>(); }
        __syncthreads();

        const uint32_t st = sb + (c & 1) * STAGE;
        const uint32_t aH = st, aL = st + A_BYTES;
        const uint32_t bH = st + 2 * A_BYTES, bL = bH + B_BYTES;

#pragma unroll
        for (int s = 0; s < 2; s++) {
            uint32_t aHf[MI][4], aLf[MI][4], bHf[NI][2], bLf[NI][2];
            const int arow = warpM + (lane & 15);
            const uint32_t acol = s * 32 + (lane >> 4) * 16;
#pragma unroll
            for (int mi = 0; mi < MI; mi++) {
                const uint32_t ao = (uint32_t)((arow + mi * 16) * AST) + acol;
                ldm4(aHf[mi], aH + ao);
                ldm4(aLf[mi], aL + ao);
            }
            const int l16 = lane & 15;
            const int brow = warpN + (l16 & 7);
            const uint32_t bcol = s * 32 + (l16 >> 3) * 16;
#pragma unroll
            for (int ni = 0; ni < NI; ni++) {
                const uint32_t bo = (uint32_t)((brow + ni * 8) * AST) + bcol;
                ldm2(bHf[ni], bH + bo);
                ldm2(bLf[ni], bL + bo);
            }
#pragma unroll
            for (int mi = 0; mi < MI; mi++)
#pragma unroll
                for (int ni = 0; ni < NI; ni++) {
                    mma16816(acc[mi][ni], aHf[mi], bHf[ni]);
                    mma16816(acc[mi][ni], aHf[mi], bLf[ni]);
                    mma16816(acc[mi][ni], aLf[mi], bHf[ni]);
                }
        }
        __syncthreads();
    }

    // ---------------- epilogue ----------------
    if (EPI == 3) {
#pragma unroll
        for (int mi = 0; mi < MI; mi++) {
#pragma unroll
            for (int h = 0; h < 2; h++) {
                const int rl = warpM + mi * 16 + (lane >> 2) + h * 8;
                const int row = mBase + rl;
                const bool rok = (row < M_valid);
                float rsum = 0.0f;
#pragma unroll
                for (int ni = 0; ni < NI; ni++) {
                    const int col0 = nBase + warpN + ni * 8 + (lane & 3) * 2;
                    float e0 = 0.f, e1 = 0.f;
                    if (rok && col0 < N_valid) {
                        e0 = __expf(acc[mi][ni][h * 2 + 0]);
                        e1 = __expf(acc[mi][ni][h * 2 + 1]);
                        const long o = (long)z * S_LEN * S_LEN + (long)row * S_LEN + col0;
                        st_split2(Dhi + o, Dlo + o, e0, e1);
                    }
                    rsum += e0 + e1;
                }
                rsum += __shfl_xor_sync(0xFFFFFFFFu, rsum, 1);
                rsum += __shfl_xor_sync(0xFFFFFFFFu, rsum, 2);
                if ((lane & 3) == 0 && rok) atomicAdd(&s_red[rl], rsum);
            }
        }
        __syncthreads();
        if (tid < 128) {
            const int row = mBase + tid;
            if (row < M_valid)
                part[(long)blockIdx.x * (H_NUM * S_LEN) + (long)z * S_LEN + row] = s_red[tid];
        }
        return;
    }

#pragma unroll
    for (int mi = 0; mi < MI; mi++) {
#pragma unroll
        for (int ni = 0; ni < NI; ni++) {
            const int rl0 = warpM + mi * 16 + (lane >> 2);
            const int col0 = nBase + warpN + ni * 8 + (lane & 3) * 2;
#pragma unroll
            for (int h = 0; h < 2; h++) {
                const int row = mBase + rl0 + h * 8;
                if (row >= M_valid) continue;
                const float v0 = acc[mi][ni][h * 2 + 0];
                const float v1 = acc[mi][ni][h * 2 + 1];
                if (EPI == 0) {
                    if (col0 < N_valid) {
                        C[(long)z * cBatch + (long)row * ldc + col0] = v0;
                        C[(long)z * cBatch + (long)row * ldc + col0 + 1] = v1;
                    }
                } else if (EPI == 1) {
                    const long o0 = ((long)z * H_NUM + (col0 >> 6)) * S_LEN * 64 + (long)row * 64 + (col0 & 63);
                    C[o0] = v0;
                    C[o0 + 1] = v1;
                } else if (EPI == 2) {
                    const float sc = invsum[(long)z * S_LEN + row];
                    const long o = (long)row * E_DIM + (long)z * 64 + col0;
                    st_split2(Dhi + o, Dlo + o, v0 * sc, v1 * sc);
                }
            }
        }
    }
}

// ---------------------------------------------------------------------------
// Small kernels
// ---------------------------------------------------------------------------
__global__ void split_kernel(const float* __restrict__ src, bf16* __restrict__ hi,
                             bf16* __restrict__ lo, long n) {
    long i = ((long)blockIdx.x * blockDim.x + threadIdx.x) * 4;
    if (i >= n) return;
    float4 v = *(const float4*)(src + i);
    float f[4] = {v.x, v.y, v.z, v.w};
#pragma unroll
    for (int j = 0; j < 4; j++) {
        bf16 h = __float2bfloat16(f[j]);
        hi[i + j] = h;
        lo[i + j] = __float2bfloat16(f[j] - __bfloat162float(h));
    }
}

// all 4 weight matrices in one launch (grid.z selects matrix)
__global__ void split4_kernel(const float* __restrict__ w0, const float* __restrict__ w1,
                              const float* __restrict__ w2, const float* __restrict__ w3,
                              bf16* __restrict__ hiB, bf16* __restrict__ loB) {
    const long nw = (long)E_DIM * E_DIM;
    const int z = blockIdx.z;
    const float* src = (z == 0) ? w0 : (z == 1) ? w1 : (z == 2) ? w2 : w3;
    bf16* hi = hiB + (long)z * nw;
    bf16* lo = loB + (long)z * nw;
    long i = ((long)blockIdx.x * blockDim.x + threadIdx.x) * 4;
    if (i >= nw) return;
    float4 v = *(const float4*)(src + i);
    float f[4] = {v.x, v.y, v.z, v.w};
#pragma unroll
    for (int j = 0; j < 4; j++) {
        bf16 h = __float2bfloat16(f[j]);
        hi[i + j] = h;
        lo[i + j] = __float2bfloat16(f[j] - __bfloat162float(h));
    }
}

__global__ void rope_split_kernel(const float* __restrict__ Q, const float* __restrict__ K,
                                  const float* __restrict__ cosp, const float* __restrict__ sinp) {
    const long total = (long)H_NUM * S_LEN * 32;
    long idx = (long)blockIdx.x * blockDim.x + threadIdx.x;
    if (idx >= total) return;
    const int d = (int)(idx & 31);
    const long hs = idx >> 5;
    const int s = (int)(hs % S_LEN);
    const long base = hs << 6;

    const float c1 = cosp[s * 64 + d], s1 = sinp[s * 64 + d];
    const float c2 = cosp[s * 64 + d + 32], s2 = sinp[s * 64 + d + 32];

    float q1 = Q[base + d], q2 = Q[base + d + 32];
    float qa = (q1 * c1 - q2 * s1) * 0.125f;
    float qb = (q2 * c2 + q1 * s2) * 0.125f;
    float k1 = K[base + d], k2 = K[base + d + 32];
    float ka = k1 * c1 - k2 * s1;
    float kb = k2 * c2 + k1 * s2;

    bf16 h;
    h = __float2bfloat16(qa); g_Qhi[base + d] = h; g_Qlo[base + d] = __float2bfloat16(qa - __bfloat162float(h));
    h = __float2bfloat16(qb); g_Qhi[base + d + 32] = h; g_Qlo[base + d + 32] = __float2bfloat16(qb - __bfloat162float(h));
    h = __float2bfloat16(ka); g_Khi[base + d] = h; g_Klo[base + d] = __float2bfloat16(ka - __bfloat162float(h));
    h = __float2bfloat16(kb); g_Khi[base + d + 32] = h; g_Klo[base + d + 32] = __float2bfloat16(kb - __bfloat162float(h));
}

__global__ void vtrans_kernel(const float* __restrict__ V) {
    __shared__ float tile[64][65];
    const int h = blockIdx.z;
    const int s0 = blockIdx.x * 64;
    const int t = threadIdx.x;
    for (int i = t; i < 4096; i += 256) {
        int s = i >> 6, d = i & 63;
        tile[s][d] = V[((long)h * S_LEN + s0 + s) * 64 + d];
    }
    __syncthreads();
    for (int i = t; i < 4096; i += 256) {
        int d = i >> 6, s = i & 63;
        float v = tile[s][d];
        bf16 hi = __float2bfloat16(v);
        long o = ((long)h * 64 + d) * S_LEN + s0 + s;
        g_Vthi[o] = hi;
        g_Vtlo[o] = __float2bfloat16(v - __bfloat162float(hi));
    }
}

__global__ void reduce_rowsum_kernel() {
    int i = blockIdx.x * blockDim.x + threadIdx.x;
    if (i >= H_NUM * S_LEN) return;
    float s = 0.f;
#pragma unroll
    for (int t = 0; t < NTILES; t++) s += g_part[t * (H_NUM * S_LEN) + i];
    g_isum[i] = 1.0f / s;
}

// one block per attention row: attn_w = (Ehi + Elo) * invsum
__global__ void normalize_kernel(float* __restrict__ W) {
    const long row = blockIdx.x;
    const float inv = g_isum[row];
    const bf16* hi = g_Ehi + row * (long)S_LEN;
    const bf16* lo = g_Elo + row * (long)S_LEN;
    float* w = W + row * (long)S_LEN;
    for (int i = threadIdx.x * 8; i < S_LEN; i += 256 * 8) {
        uint4 h4 = *(const uint4*)(hi + i);
        uint4 l4 = *(const uint4*)(lo + i);
        const uint32_t hh[4] = {h4.x, h4.y, h4.z, h4.w};
        const uint32_t ll[4] = {l4.x, l4.y, l4.z, l4.w};
        float o[8];
#pragma unroll
        for (int j = 0; j < 4; j++) {
            __nv_bfloat162 hb = *(const __nv_bfloat162*)&hh[j];
            __nv_bfloat162 lb = *(const __nv_bfloat162*)&ll[j];
            o[j * 2 + 0] = (__bfloat162float(hb.x) + __bfloat162float(lb.x)) * inv;
            o[j * 2 + 1] = (__bfloat162float(hb.y) + __bfloat162float(lb.y)) * inv;
        }
        *(float4*)(w + i)     = make_float4(o[0], o[1], o[2], o[3]);
        *(float4*)(w + i + 4) = make_float4(o[4], o[5], o[6], o[7]);
    }
}

// ---------------------------------------------------------------------------
// Launch
// ---------------------------------------------------------------------------
extern "C" void kernel_launch(void* const* d_in, const int* in_sizes, int n_in,
                              void* d_out, int out_size) {
    const float* hidden = (const float*)d_in[0];
    const float* cosp   = (const float*)d_in[1];
    const float* sinp   = (const float*)d_in[2];
    const float* w[4]   = {(const float*)d_in[3], (const float*)d_in[4],
                           (const float*)d_in[5], (const float*)d_in[6]};

    float* out    = (float*)d_out;
    float* attn_w = out + (long)S_LEN * E_DIM;

    float* qkv; cudaGetSymbolAddress((void**)&qkv, g_qkv);
    bf16 *Hhi, *Hlo, *Whi, *Wlo, *Qhi, *Qlo, *Khi, *Klo, *Vthi, *Vtlo, *Ehi, *Elo, *AOhi, *AOlo;
    float *part, *isum;
    cudaGetSymbolAddress((void**)&Hhi, g_Hhi);  cudaGetSymbolAddress((void**)&Hlo, g_Hlo);
    cudaGetSymbolAddress((void**)&Whi, g_Whi);  cudaGetSymbolAddress((void**)&Wlo, g_Wlo);
    cudaGetSymbolAddress((void**)&Qhi, g_Qhi);  cudaGetSymbolAddress((void**)&Qlo, g_Qlo);
    cudaGetSymbolAddress((void**)&Khi, g_Khi);  cudaGetSymbolAddress((void**)&Klo, g_Klo);
    cudaGetSymbolAddress((void**)&Vthi, g_Vthi); cudaGetSymbolAddress((void**)&Vtlo, g_Vtlo);
    cudaGetSymbolAddress((void**)&Ehi, g_Ehi);  cudaGetSymbolAddress((void**)&Elo, g_Elo);
    cudaGetSymbolAddress((void**)&AOhi, g_AOhi); cudaGetSymbolAddress((void**)&AOlo, g_AOlo);
    cudaGetSymbolAddress((void**)&part, g_part); cudaGetSymbolAddress((void**)&isum, g_isum);

    // one-time side stream + fork/join events (host resources, not device memory)
    static cudaStream_t s1 = nullptr;
    static cudaEvent_t evFork = nullptr, evJoin = nullptr;
    if (!s1) {
        cudaStreamCreateWithFlags(&s1, cudaStreamNonBlocking);
        cudaEventCreateWithFlags(&evFork, cudaEventDisableTiming);
        cudaEventCreateWithFlags(&evJoin, cudaEventDisableTiming);
    }

    const int SMEM128 = 2 * (2 * 128 * 80 + 2 * 128 * 80);  // 81920
    const int SMEM64  = 2 * (2 * 128 * 80 + 2 * 64 * 80);   // 61440
    cudaFuncSetAttribute(mma_gemm<128, 0>, cudaFuncAttributeMaxDynamicSharedMemorySize, SMEM128);
    cudaFuncSetAttribute(mma_gemm<128, 1>, cudaFuncAttributeMaxDynamicSharedMemorySize, SMEM128);
    cudaFuncSetAttribute(mma_gemm<128, 3>, cudaFuncAttributeMaxDynamicSharedMemorySize, SMEM128);
    cudaFuncSetAttribute(mma_gemm<64, 2>,  cudaFuncAttributeMaxDynamicSharedMemorySize, SMEM64);

    // 1) bf16 splits of hidden + weights (weights in one grid.z=4 launch)
    {
        long n = (long)S_LEN * E_DIM;
        split_kernel<<<(int)((n / 4 + 255) / 256), 256>>>(hidden, Hhi, Hlo, n);
        long nw = (long)E_DIM * E_DIM;
        dim3 gw((unsigned)((nw / 4 + 255) / 256), 1, 4);
        split4_kernel<<<gw, 256>>>(w[0], w[1], w[2], w[3], Whi, Wlo);
    }

    // 2) QKV projections, batched over z={q,k,v} (head-major fp32)
    {
        dim3 g(E_DIM / 128, (S_LEN + 127) / 128, 3);
        mma_gemm<128, 1><<<g, 256, SMEM128>>>(Hhi, Hlo, E_DIM, 0,
                                              Whi, Wlo, E_DIM, (long)E_DIM * E_DIM,
                                              qkv, 0, 0, nullptr, nullptr, nullptr, nullptr,
                                              32, S_LEN, E_DIM);
    }

    // 3) RoPE + split (1/sqrt(D) folded into Q); V transpose + split
    {
        long total = (long)H_NUM * S_LEN * 32;
        const long HSD = (long)H_NUM * S_LEN * D_DIM;
        rope_split_kernel<<<(int)((total + 255) / 256), 256>>>(qkv, qkv + HSD, cosp, sinp);
        dim3 gv(S_LEN / 64, 1, H_NUM);
        vtrans_kernel<<<gv, 256>>>(qkv + 2 * HSD);
    }

    // 4) score GEMM: E = exp(Q K^T / 8) (bf16 splits) + partial row sums
    {
        dim3 g((S_LEN + 127) / 128, (S_LEN + 127) / 128, H_NUM);
        mma_gemm<128, 3><<<g, 256, SMEM128>>>(Qhi, Qlo, 64, (long)S_LEN * 64,
                                              Khi, Klo, 64, (long)S_LEN * 64,
                                              nullptr, 0, 0, Ehi, Elo, nullptr, part,
                                              2, S_LEN, S_LEN);
    }

    // 5) row sums -> inverse
    reduce_rowsum_kernel<<<(H_NUM * S_LEN + 255) / 256, 256>>>();

    // 6) FORK: normalize (BW-bound) runs on side stream, overlapped with PV+out
    cudaEventRecord(evFork, 0);
    cudaStreamWaitEvent(s1, evFork, 0);
    normalize_kernel<<<H_NUM * S_LEN, 256, 0, s1>>>(attn_w);
    cudaEventRecord(evJoin, s1);

    // 7) PV (unnormalized E, scaled epilogue) -> AO bf16 splits  [main stream]
    {
        dim3 g(1, (S_LEN + 127) / 128, H_NUM);
        mma_gemm<64, 2><<<g, 256, SMEM64>>>(Ehi, Elo, S_LEN, (long)S_LEN * S_LEN,
                                            Vthi, Vtlo, S_LEN, (long)64 * S_LEN,
                                            nullptr, 0, 0, AOhi, AOlo, isum, nullptr,
                                            98, S_LEN, 64);
    }

    // 8) out = AO Wo^T  [main stream]
    {
        dim3 g(E_DIM / 128, (S_LEN + 127) / 128, 1);
        long nw = (long)E_DIM * E_DIM;
        mma_gemm<128, 0><<<g, 256, SMEM128>>>(AOhi, AOlo, E_DIM, 0,
                                              Whi + 3 * nw, Wlo + 3 * nw, E_DIM, 0,
                                              out, E_DIM, 0, nullptr, nullptr, nullptr, nullptr,
                                              32, S_LEN, E_DIM);
    }

    // 9) JOIN side stream back into the main stream
    cudaStreamWaitEvent(0, evJoin, 0);
}

// round 8
// speedup vs baseline: 1.2192x; 1.1560x over previous
#include <cuda_runtime.h>
#include <cuda_bf16.h>
#include <cuda_fp16.h>
#include <math.h>
#include <stdint.h>

#define S_LEN 3136
#define E_DIM 1024
#define H_NUM 16
#define D_DIM 64
#define NTILES 25   // ceil(3136/128)

typedef __nv_bfloat16 bf16;

// ---------------------------------------------------------------------------
// Device scratch (allocation is forbidden)
// ---------------------------------------------------------------------------
__device__ float g_qkv[3][H_NUM * S_LEN * D_DIM];   // fp32 head-major q,k,v

__device__ __align__(16) bf16 g_Hhi[S_LEN * E_DIM];
__device__ __align__(16) bf16 g_Hlo[S_LEN * E_DIM];
__device__ __align__(16) bf16 g_Whi[4][E_DIM * E_DIM];
__device__ __align__(16) bf16 g_Wlo[4][E_DIM * E_DIM];
__device__ __align__(16) bf16 g_Qhi[H_NUM * S_LEN * D_DIM];
__device__ __align__(16) bf16 g_Qlo[H_NUM * S_LEN * D_DIM];
__device__ __align__(16) bf16 g_Khi[H_NUM * S_LEN * D_DIM];
__device__ __align__(16) bf16 g_Klo[H_NUM * S_LEN * D_DIM];
__device__ __align__(16) __half g_Vthi[H_NUM * D_DIM * S_LEN];   // [h][d][s] fp16
__device__ __align__(16) __half g_Vtlo[H_NUM * D_DIM * S_LEN];
__device__ __align__(16) __half g_E[(long)H_NUM * S_LEN * S_LEN]; // unnormalized exp, fp16
__device__ __align__(16) bf16 g_AOhi[S_LEN * E_DIM];
__device__ __align__(16) bf16 g_AOlo[S_LEN * E_DIM];
__device__ float g_part[NTILES * H_NUM * S_LEN];   // per-(ntile,row) partial sums
__device__ float g_isum[H_NUM * S_LEN];            // 1 / rowsum

// ---------------------------------------------------------------------------
// PTX helpers (sm_80-era: cp.async + ldmatrix + mma.sync)
// ---------------------------------------------------------------------------
__device__ __forceinline__ uint32_t smem_u32(const void* p) {
    uint32_t a;
    asm("{ .reg .u64 t; cvta.to.shared.u64 t, %1; cvt.u32.u64 %0, t; }" : "=r"(a) : "l"(p));
    return a;
}
__device__ __forceinline__ void cp16(uint32_t dst, const void* src, int srcsize) {
    asm volatile("cp.async.cg.shared.global [%0], [%1], 16, %2;"
                 :: "r"(dst), "l"(src), "r"(srcsize));
}
__device__ __forceinline__ void cpcommit() { asm volatile("cp.async.commit_group;"); }
template <int N> __device__ __forceinline__ void cpwait() {
    asm volatile("cp.async.wait_group %0;" :: "n"(N));
}
__device__ __forceinline__ void ldm4(uint32_t* r, uint32_t a) {
    asm volatile("ldmatrix.sync.aligned.m8n8.x4.shared.b16 {%0,%1,%2,%3}, [%4];"
                 : "=r"(r[0]), "=r"(r[1]), "=r"(r[2]), "=r"(r[3]) : "r"(a));
}
__device__ __forceinline__ void ldm2(uint32_t* r, uint32_t a) {
    asm volatile("ldmatrix.sync.aligned.m8n8.x2.shared.b16 {%0,%1}, [%2];"
                 : "=r"(r[0]), "=r"(r[1]) : "r"(a));
}
template <bool F16>
__device__ __forceinline__ void mma16816(float* d, const uint32_t* a, const uint32_t* b) {
    if constexpr (F16) {
        asm volatile("mma.sync.aligned.m16n8k16.row.col.f32.f16.f16.f32 "
                     "{%0,%1,%2,%3}, {%4,%5,%6,%7}, {%8,%9}, {%0,%1,%2,%3};"
                     : "+f"(d[0]), "+f"(d[1]), "+f"(d[2]), "+f"(d[3])
                     : "r"(a[0]), "r"(a[1]), "r"(a[2]), "r"(a[3]), "r"(b[0]), "r"(b[1]));
    } else {
        asm volatile("mma.sync.aligned.m16n8k16.row.col.f32.bf16.bf16.f32 "
                     "{%0,%1,%2,%3}, {%4,%5,%6,%7}, {%8,%9}, {%0,%1,%2,%3};"
                     : "+f"(d[0]), "+f"(d[1]), "+f"(d[2]), "+f"(d[3])
                     : "r"(a[0]), "r"(a[1]), "r"(a[2]), "r"(a[3]), "r"(b[0]), "r"(b[1]));
    }
}
__device__ __forceinline__ void st_split2(bf16* hi, bf16* lo, float a, float b) {
    __nv_bfloat162 h;
    h.x = __float2bfloat16(a);
    h.y = __float2bfloat16(b);
    *(__nv_bfloat162*)hi = h;
    __nv_bfloat162 l;
    l.x = __float2bfloat16(a - __bfloat162float(h.x));
    l.y = __float2bfloat16(b - __bfloat162float(h.y));
    *(__nv_bfloat162*)lo = l;
}

// ---------------------------------------------------------------------------
// TN GEMM via mma.sync, 2-stage cp.async double buffer.
//  F16: use f16 mma (else bf16).  A_DUAL: A has hi+lo (3 passes) else single A
//  (2 passes: A*Bhi + A*Blo).
// EPI 0: fp32 C[z*cBatch + m*ldc + n]
// EPI 1: fp32 head-major qkv: C[(z*H + (n>>6))*S*64 + m*64 + (n&63)]
// EPI 2: PV: AO bf16 split at [m*E + z*64 + n], scaled by invsum[z*S+m]
// EPI 3: score: e=exp(v) -> fp16 E (via Dhi reinterpreted); rounded row sums
// ---------------------------------------------------------------------------
template <int N_TILE, int EPI, bool F16, bool A_DUAL>
__global__ void __launch_bounds__(256, 1) mma_gemm(
    const bf16* __restrict__ Ahi, const bf16* __restrict__ Alo, long aRow, long aBatch,
    const bf16* __restrict__ Bhi, const bf16* __restrict__ Blo, long bRow, long bBatch,
    float* __restrict__ C, long ldc, long cBatch,
    bf16* __restrict__ Dhi, bf16* __restrict__ Dlo,
    const float* __restrict__ invsum, float* __restrict__ part,
    int kChunks, int M_valid, int N_valid) {

    constexpr int AST = 80;                 // smem bytes per 32-elt row (64 + 16 pad)
    constexpr int A_BYTES = 128 * AST;
    constexpr int A_TOT = (A_DUAL ? 2 : 1) * A_BYTES;
    constexpr int B_BYTES = N_TILE * AST;
    constexpr int STAGE = A_TOT + 2 * B_BYTES;

    extern __shared__ char smem[];
    const uint32_t sb = smem_u32(smem);
    __shared__ float s_red[128];

    const int tid = threadIdx.x;
    const int wid = tid >> 5, lane = tid & 31;
    constexpr int WC = (N_TILE == 128) ? 4 : 2;
    constexpr int WM = (N_TILE == 128) ? 64 : 32;
    constexpr int WN = 32;
    constexpr int MI = WM / 16, NI = WN / 8;
    const int warpM = (wid / WC) * WM;
    const int warpN = (wid % WC) * WN;

    const int mBase = blockIdx.y * 128;
    const int nBase = blockIdx.x * N_TILE;
    const int z = blockIdx.z;
    Ahi += aBatch * z;
    if (A_DUAL) Alo += aBatch * z;
    Bhi += bBatch * z; Blo += bBatch * z;

    float acc[MI][NI][4];
#pragma unroll
    for (int i = 0; i < MI; i++)
#pragma unroll
        for (int j = 0; j < NI; j++)
#pragma unroll
            for (int q = 0; q < 4; q++) acc[i][j][q] = 0.0f;

    if (EPI == 3) {
        if (tid < 128) s_red[tid] = 0.0f;
    }

    auto issue_loads = [&](int c) {
        const long k0 = (long)c * 32;
        const uint32_t st = sb + (c & 1) * STAGE;
        for (int i = tid; i < 512; i += 256) {
            const int r = i >> 2, u = i & 3;
            const int row = mBase + r;
            const int ok = (row < M_valid) ? 16 : 0;
            const long srow = (row < M_valid) ? row : (M_valid - 1);
            const long off = srow * aRow + k0 + u * 8;
            const uint32_t dst = st + r * AST + u * 16;
            cp16(dst, Ahi + off, ok);
            if constexpr (A_DUAL) cp16(dst + A_BYTES, Alo + off, ok);
        }
        for (int i = tid; i < N_TILE * 4; i += 256) {
            const int r = i >> 2, u = i & 3;
            const int row = nBase + r;
            const int ok = (row < N_valid) ? 16 : 0;
            const long srow = (row < N_valid) ? row : (N_valid - 1);
            const long off = srow * bRow + k0 + u * 8;
            const uint32_t dst = st + A_TOT + r * AST + u * 16;
            cp16(dst, Bhi + off, ok);
            cp16(dst + B_BYTES, Blo + off, ok);
        }
        cpcommit();
    };

    issue_loads(0);

    for (int c = 0; c < kChunks; c++) {
        if (c + 1 < kChunks) { issue_loads(c + 1); cpwait<1>(); }
        else                 { cpwait<0>(); }
        __syncthreads();

        const uint32_t st = sb + (c & 1) * STAGE;
        const uint32_t aH = st, aL = st + A_BYTES;
        const uint32_t bH = st + A_TOT, bL = bH + B_BYTES;

#pragma unroll
        for (int s = 0; s < 2; s++) {
            uint32_t aHf[MI][4], aLf[MI][4], bHf[NI][2], bLf[NI][2];
            const int arow = warpM + (lane & 15);
            const uint32_t acol = s * 32 + (lane >> 4) * 16;
#pragma unroll
            for (int mi = 0; mi < MI; mi++) {
                const uint32_t ao = (uint32_t)((arow + mi * 16) * AST) + acol;
                ldm4(aHf[mi], aH + ao);
                if constexpr (A_DUAL) ldm4(aLf[mi], aL + ao);
            }
            const int l16 = lane & 15;
            const int brow = warpN + (l16 & 7);
            const uint32_t bcol = s * 32 + (l16 >> 3) * 16;
#pragma unroll
            for (int ni = 0; ni < NI; ni++) {
                const uint32_t bo = (uint32_t)((brow + ni * 8) * AST) + bcol;
                ldm2(bHf[ni], bH + bo);
                ldm2(bLf[ni], bL + bo);
            }
#pragma unroll
            for (int mi = 0; mi < MI; mi++)
#pragma unroll
                for (int ni = 0; ni < NI; ni++) {
                    mma16816<F16>(acc[mi][ni], aHf[mi], bHf[ni]);
                    mma16816<F16>(acc[mi][ni], aHf[mi], bLf[ni]);
                    if constexpr (A_DUAL) mma16816<F16>(acc[mi][ni], aLf[mi], bHf[ni]);
                }
        }
        __syncthreads();
    }

    // ---------------- epilogue ----------------
    if (EPI == 3) {
        __half* Eout = reinterpret_cast<__half*>(Dhi);
#pragma unroll
        for (int mi = 0; mi < MI; mi++) {
#pragma unroll
            for (int h = 0; h < 2; h++) {
                const int rl = warpM + mi * 16 + (lane >> 2) + h * 8;
                const int row = mBase + rl;
                const bool rok = (row < M_valid);
                float rsum = 0.0f;
#pragma unroll
                for (int ni = 0; ni < NI; ni++) {
                    const int col0 = nBase + warpN + ni * 8 + (lane & 3) * 2;
                    if (rok && col0 < N_valid) {
                        const float e0 = __expf(acc[mi][ni][h * 2 + 0]);
                        const float e1 = __expf(acc[mi][ni][h * 2 + 1]);
                        const __half2 hv = __floats2half2_rn(e0, e1);
                        const long o = (long)z * S_LEN * S_LEN + (long)row * S_LEN + col0;
                        *reinterpret_cast<__half2*>(Eout + o) = hv;
                        // sum the ROUNDED values so rows normalize to exactly 1
                        rsum += __low2float(hv) + __high2float(hv);
                    }
                }
                rsum += __shfl_xor_sync(0xFFFFFFFFu, rsum, 1);
                rsum += __shfl_xor_sync(0xFFFFFFFFu, rsum, 2);
                if ((lane & 3) == 0 && rok) atomicAdd(&s_red[rl], rsum);
            }
        }
        __syncthreads();
        if (tid < 128) {
            const int row = mBase + tid;
            if (row < M_valid)
                part[(long)blockIdx.x * (H_NUM * S_LEN) + (long)z * S_LEN + row] = s_red[tid];
        }
        return;
    }

#pragma unroll
    for (int mi = 0; mi < MI; mi++) {
#pragma unroll
        for (int ni = 0; ni < NI; ni++) {
            const int rl0 = warpM + mi * 16 + (lane >> 2);
            const int col0 = nBase + warpN + ni * 8 + (lane & 3) * 2;
#pragma unroll
            for (int h = 0; h < 2; h++) {
                const int row = mBase + rl0 + h * 8;
                if (row >= M_valid) continue;
                const float v0 = acc[mi][ni][h * 2 + 0];
                const float v1 = acc[mi][ni][h * 2 + 1];
                if (EPI == 0) {
                    if (col0 < N_valid) {
                        C[(long)z * cBatch + (long)row * ldc + col0] = v0;
                        C[(long)z * cBatch + (long)row * ldc + col0 + 1] = v1;
                    }
                } else if (EPI == 1) {
                    const long o0 = ((long)z * H_NUM + (col0 >> 6)) * S_LEN * 64 + (long)row * 64 + (col0 & 63);
                    C[o0] = v0;
                    C[o0 + 1] = v1;
                } else if (EPI == 2) {
                    const float sc = invsum[(long)z * S_LEN + row];
                    const long o = (long)row * E_DIM + (long)z * 64 + col0;
                    st_split2(Dhi + o, Dlo + o, v0 * sc, v1 * sc);
                }
            }
        }
    }
}

// ---------------------------------------------------------------------------
// Small kernels
// ---------------------------------------------------------------------------
__global__ void split_kernel(const float* __restrict__ src, bf16* __restrict__ hi,
                             bf16* __restrict__ lo, long n) {
    long i = ((long)blockIdx.x * blockDim.x + threadIdx.x) * 4;
    if (i >= n) return;
    float4 v = *(const float4*)(src + i);
    float f[4] = {v.x, v.y, v.z, v.w};
#pragma unroll
    for (int j = 0; j < 4; j++) {
        bf16 h = __float2bfloat16(f[j]);
        hi[i + j] = h;
        lo[i + j] = __float2bfloat16(f[j] - __bfloat162float(h));
    }
}

__global__ void split4_kernel(const float* __restrict__ w0, const float* __restrict__ w1,
                              const float* __restrict__ w2, const float* __restrict__ w3,
                              bf16* __restrict__ hiB, bf16* __restrict__ loB) {
    const long nw = (long)E_DIM * E_DIM;
    const int z = blockIdx.z;
    const float* src = (z == 0) ? w0 : (z == 1) ? w1 : (z == 2) ? w2 : w3;
    bf16* hi = hiB + (long)z * nw;
    bf16* lo = loB + (long)z * nw;
    long i = ((long)blockIdx.x * blockDim.x + threadIdx.x) * 4;
    if (i >= nw) return;
    float4 v = *(const float4*)(src + i);
    float f[4] = {v.x, v.y, v.z, v.w};
#pragma unroll
    for (int j = 0; j < 4; j++) {
        bf16 h = __float2bfloat16(f[j]);
        hi[i + j] = h;
        lo[i + j] = __float2bfloat16(f[j] - __bfloat162float(h));
    }
}

__global__ void rope_split_kernel(const float* __restrict__ Q, const float* __restrict__ K,
                                  const float* __restrict__ cosp, const float* __restrict__ sinp) {
    const long total = (long)H_NUM * S_LEN * 32;
    long idx = (long)blockIdx.x * blockDim.x + threadIdx.x;
    if (idx >= total) return;
    const int d = (int)(idx & 31);
    const long hs = idx >> 5;
    const int s = (int)(hs % S_LEN);
    const long base = hs << 6;

    const float c1 = cosp[s * 64 + d], s1 = sinp[s * 64 + d];
    const float c2 = cosp[s * 64 + d + 32], s2 = sinp[s * 64 + d + 32];

    float q1 = Q[base + d], q2 = Q[base + d + 32];
    float qa = (q1 * c1 - q2 * s1) * 0.125f;
    float qb = (q2 * c2 + q1 * s2) * 0.125f;
    float k1 = K[base + d], k2 = K[base + d + 32];
    float ka = k1 * c1 - k2 * s1;
    float kb = k2 * c2 + k1 * s2;

    bf16 h;
    h = __float2bfloat16(qa); g_Qhi[base + d] = h; g_Qlo[base + d] = __float2bfloat16(qa - __bfloat162float(h));
    h = __float2bfloat16(qb); g_Qhi[base + d + 32] = h; g_Qlo[base + d + 32] = __float2bfloat16(qb - __bfloat162float(h));
    h = __float2bfloat16(ka); g_Khi[base + d] = h; g_Klo[base + d] = __float2bfloat16(ka - __bfloat162float(h));
    h = __float2bfloat16(kb); g_Khi[base + d + 32] = h; g_Klo[base + d + 32] = __float2bfloat16(kb - __bfloat162float(h));
}

// V transpose + fp16 split: fp32 [h][s][64] -> fp16 [h][d][s] hi/lo
__global__ void vtrans_kernel(const float* __restrict__ V) {
    __shared__ float tile[64][65];
    const int h = blockIdx.z;
    const int s0 = blockIdx.x * 64;
    const int t = threadIdx.x;
    for (int i = t; i < 4096; i += 256) {
        int s = i >> 6, d = i & 63;
        tile[s][d] = V[((long)h * S_LEN + s0 + s) * 64 + d];
    }
    __syncthreads();
    for (int i = t; i < 4096; i += 256) {
        int d = i >> 6, s = i & 63;
        float v = tile[s][d];
        __half hi = __float2half_rn(v);
        long o = ((long)h * 64 + d) * S_LEN + s0 + s;
        g_Vthi[o] = hi;
        g_Vtlo[o] = __float2half_rn(v - __half2float(hi));
    }
}

__global__ void reduce_rowsum_kernel() {
    int i = blockIdx.x * blockDim.x + threadIdx.x;
    if (i >= H_NUM * S_LEN) return;
    float s = 0.f;
#pragma unroll
    for (int t = 0; t < NTILES; t++) s += g_part[t * (H_NUM * S_LEN) + i];
    g_isum[i] = 1.0f / s;
}

// one block per attention row: attn_w = E(fp16) * invsum
__global__ void normalize_kernel(float* __restrict__ W) {
    const long row = blockIdx.x;
    const float inv = g_isum[row];
    const __half* e = g_E + row * (long)S_LEN;
    float* w = W + row * (long)S_LEN;
    for (int i = threadIdx.x * 8; i < S_LEN; i += 256 * 8) {
        uint4 h4 = *(const uint4*)(e + i);          // 8 halves
        const uint32_t hh[4] = {h4.x, h4.y, h4.z, h4.w};
        float o[8];
#pragma unroll
        for (int j = 0; j < 4; j++) {
            __half2 hb = *(const __half2*)&hh[j];
            o[j * 2 + 0] = __low2float(hb) * inv;
            o[j * 2 + 1] = __high2float(hb) * inv;
        }
        *(float4*)(w + i)     = make_float4(o[0], o[1], o[2], o[3]);
        *(float4*)(w + i + 4) = make_float4(o[4], o[5], o[6], o[7]);
    }
}

// ---------------------------------------------------------------------------
// Launch
// ---------------------------------------------------------------------------
extern "C" void kernel_launch(void* const* d_in, const int* in_sizes, int n_in,
                              void* d_out, int out_size) {
    const float* hidden = (const float*)d_in[0];
    const float* cosp   = (const float*)d_in[1];
    const float* sinp   = (const float*)d_in[2];
    const float* w[4]   = {(const float*)d_in[3], (const float*)d_in[4],
                           (const float*)d_in[5], (const float*)d_in[6]};

    float* out    = (float*)d_out;
    float* attn_w = out + (long)S_LEN * E_DIM;

    float* qkv; cudaGetSymbolAddress((void**)&qkv, g_qkv);
    bf16 *Hhi, *Hlo, *Whi, *Wlo, *Qhi, *Qlo, *Khi, *Klo, *AOhi, *AOlo;
    __half *Vthi, *Vtlo, *E;
    float *part, *isum;
    cudaGetSymbolAddress((void**)&Hhi, g_Hhi);  cudaGetSymbolAddress((void**)&Hlo, g_Hlo);
    cudaGetSymbolAddress((void**)&Whi, g_Whi);  cudaGetSymbolAddress((void**)&Wlo, g_Wlo);
    cudaGetSymbolAddress((void**)&Qhi, g_Qhi);  cudaGetSymbolAddress((void**)&Qlo, g_Qlo);
    cudaGetSymbolAddress((void**)&Khi, g_Khi);  cudaGetSymbolAddress((void**)&Klo, g_Klo);
    cudaGetSymbolAddress((void**)&Vthi, g_Vthi); cudaGetSymbolAddress((void**)&Vtlo, g_Vtlo);
    cudaGetSymbolAddress((void**)&E, g_E);
    cudaGetSymbolAddress((void**)&AOhi, g_AOhi); cudaGetSymbolAddress((void**)&AOlo, g_AOlo);
    cudaGetSymbolAddress((void**)&part, g_part); cudaGetSymbolAddress((void**)&isum, g_isum);

    static cudaStream_t s1 = nullptr;
    static cudaEvent_t evFork = nullptr, evJoin = nullptr;
    if (!s1) {
        cudaStreamCreateWithFlags(&s1, cudaStreamNonBlocking);
        cudaEventCreateWithFlags(&evFork, cudaEventDisableTiming);
        cudaEventCreateWithFlags(&evJoin, cudaEventDisableTiming);
    }

    const int SMEM128 = 2 * (2 * 128 * 80 + 2 * 128 * 80);  // 81920 (A dual)
    const int SMEM_PV = 2 * (1 * 128 * 80 + 2 * 64 * 80);   // 40960 (A single)
    cudaFuncSetAttribute((const void*)mma_gemm<128, 0, false, true>, cudaFuncAttributeMaxDynamicSharedMemorySize, SMEM128);
    cudaFuncSetAttribute((const void*)mma_gemm<128, 1, false, true>, cudaFuncAttributeMaxDynamicSharedMemorySize, SMEM128);
    cudaFuncSetAttribute((const void*)mma_gemm<128, 3, false, true>, cudaFuncAttributeMaxDynamicSharedMemorySize, SMEM128);
    cudaFuncSetAttribute((const void*)mma_gemm<64, 2, true, false>,  cudaFuncAttributeMaxDynamicSharedMemorySize, SMEM_PV);

    // 1) bf16 splits of hidden + weights
    {
        long n = (long)S_LEN * E_DIM;
        split_kernel<<<(int)((n / 4 + 255) / 256), 256>>>(hidden, Hhi, Hlo, n);
        long nw = (long)E_DIM * E_DIM;
        dim3 gw((unsigned)((nw / 4 + 255) / 256), 1, 4);
        split4_kernel<<<gw, 256>>>(w[0], w[1], w[2], w[3], Whi, Wlo);
    }

    // 2) QKV projections, batched over z={q,k,v} (head-major fp32)
    {
        dim3 g(E_DIM / 128, (S_LEN + 127) / 128, 3);
        mma_gemm<128, 1, false, true><<<g, 256, SMEM128>>>(Hhi, Hlo, E_DIM, 0,
                                              Whi, Wlo, E_DIM, (long)E_DIM * E_DIM,
                                              qkv, 0, 0, nullptr, nullptr, nullptr, nullptr,
                                              32, S_LEN, E_DIM);
    }

    // 3) RoPE + split (1/sqrt(D) folded into Q); V transpose + fp16 split
    {
        long total = (long)H_NUM * S_LEN * 32;
        const long HSD = (long)H_NUM * S_LEN * D_DIM;
        rope_split_kernel<<<(int)((total + 255) / 256), 256>>>(qkv, qkv + HSD, cosp, sinp);
        dim3 gv(S_LEN / 64, 1, H_NUM);
        vtrans_kernel<<<gv, 256>>>(qkv + 2 * HSD);
    }

    // 4) score GEMM: E = exp(Q K^T / 8) (fp16) + rounded partial row sums
    {
        dim3 g((S_LEN + 127) / 128, (S_LEN + 127) / 128, H_NUM);
        mma_gemm<128, 3, false, true><<<g, 256, SMEM128>>>(Qhi, Qlo, 64, (long)S_LEN * 64,
                                              Khi, Klo, 64, (long)S_LEN * 64,
                                              nullptr, 0, 0, (bf16*)E, nullptr, nullptr, part,
                                              2, S_LEN, S_LEN);
    }

    // 5) row sums -> inverse
    reduce_rowsum_kernel<<<(H_NUM * S_LEN + 255) / 256, 256>>>();

    // 6) FORK: normalize (BW-bound) on side stream, overlapped with PV+out
    cudaEventRecord(evFork, 0);
    cudaStreamWaitEvent(s1, evFork, 0);
    normalize_kernel<<<H_NUM * S_LEN, 256, 0, s1>>>(attn_w);
    cudaEventRecord(evJoin, s1);

    // 7) PV: E(fp16, single) x Vt(fp16 hi/lo) -> AO bf16 splits  [main stream]
    {
        dim3 g(1, (S_LEN + 127) / 128, H_NUM);
        mma_gemm<64, 2, true, false><<<g, 256, SMEM_PV>>>(
            (const bf16*)E, nullptr, S_LEN, (long)S_LEN * S_LEN,
            (const bf16*)Vthi, (const bf16*)Vtlo, S_LEN, (long)64 * S_LEN,
            nullptr, 0, 0, AOhi, AOlo, isum, nullptr,
            98, S_LEN, 64);
    }

    // 8) out = AO Wo^T  [main stream]
    {
        dim3 g(E_DIM / 128, (S_LEN + 127) / 128, 1);
        long nw = (long)E_DIM * E_DIM;
        mma_gemm<128, 0, false, true><<<g, 256, SMEM128>>>(AOhi, AOlo, E_DIM, 0,
                                              Whi + 3 * nw, Wlo + 3 * nw, E_DIM, 0,
                                              out, E_DIM, 0, nullptr, nullptr, nullptr, nullptr,
                                              32, S_LEN, E_DIM);
    }

    // 9) JOIN
    cudaStreamWaitEvent(0, evJoin, 0);
}

// round 9
// speedup vs baseline: 1.4188x; 1.1637x over previous
#include <cuda_runtime.h>
#include <cuda_bf16.h>
#include <cuda_fp16.h>
#include <math.h>
#include <stdint.h>

#define S_LEN 3136
#define E_DIM 1024
#define H_NUM 16
#define D_DIM 64
#define NTILES 25   // ceil(3136/128)

typedef __nv_bfloat16 bf16;

// ---------------------------------------------------------------------------
// Device scratch (allocation is forbidden)
// ---------------------------------------------------------------------------
__device__ float g_qkv[3][H_NUM * S_LEN * D_DIM];   // fp32 head-major q,k,v

__device__ __align__(16) __half g_Hh[S_LEN * E_DIM];            // hidden fp16 single
__device__ __align__(16) __half g_Whi[4][E_DIM * E_DIM];        // weights fp16 hi
__device__ __align__(16) __half g_Wlo[4][E_DIM * E_DIM];        // weights fp16 lo
__device__ __align__(16) __half g_Qh[H_NUM * S_LEN * D_DIM];    // q fp16 single (scaled)
__device__ __align__(16) __half g_Kh[H_NUM * S_LEN * D_DIM];    // k fp16 single
__device__ __align__(16) __half g_Vthi[H_NUM * D_DIM * S_LEN];  // [h][d][s] fp16 hi
__device__ __align__(16) __half g_Vtlo[H_NUM * D_DIM * S_LEN];  // fp16 lo
__device__ __align__(16) __half g_E[(long)H_NUM * S_LEN * S_LEN]; // unnormalized exp, fp16
__device__ __align__(16) __half g_AO[S_LEN * E_DIM];            // attn out fp16 single
__device__ float g_part[NTILES * H_NUM * S_LEN];
__device__ float g_isum[H_NUM * S_LEN];

// ---------------------------------------------------------------------------
// PTX helpers
// ---------------------------------------------------------------------------
__device__ __forceinline__ uint32_t smem_u32(const void* p) {
    uint32_t a;
    asm("{ .reg .u64 t; cvta.to.shared.u64 t, %1; cvt.u32.u64 %0, t; }" : "=r"(a) : "l"(p));
    return a;
}
__device__ __forceinline__ void cp16(uint32_t dst, const void* src, int srcsize) {
    asm volatile("cp.async.cg.shared.global [%0], [%1], 16, %2;"
                 :: "r"(dst), "l"(src), "r"(srcsize));
}
__device__ __forceinline__ void cpcommit() { asm volatile("cp.async.commit_group;"); }
template <int N> __device__ __forceinline__ void cpwait() {
    asm volatile("cp.async.wait_group %0;" :: "n"(N));
}
__device__ __forceinline__ void ldm4(uint32_t* r, uint32_t a) {
    asm volatile("ldmatrix.sync.aligned.m8n8.x4.shared.b16 {%0,%1,%2,%3}, [%4];"
                 : "=r"(r[0]), "=r"(r[1]), "=r"(r[2]), "=r"(r[3]) : "r"(a));
}
__device__ __forceinline__ void ldm2(uint32_t* r, uint32_t a) {
    asm volatile("ldmatrix.sync.aligned.m8n8.x2.shared.b16 {%0,%1}, [%2];"
                 : "=r"(r[0]), "=r"(r[1]) : "r"(a));
}
__device__ __forceinline__ void mma16816(float* d, const uint32_t* a, const uint32_t* b) {
    asm volatile("mma.sync.aligned.m16n8k16.row.col.f32.f16.f16.f32 "
                 "{%0,%1,%2,%3}, {%4,%5,%6,%7}, {%8,%9}, {%0,%1,%2,%3};"
                 : "+f"(d[0]), "+f"(d[1]), "+f"(d[2]), "+f"(d[3])
                 : "r"(a[0]), "r"(a[1]), "r"(a[2]), "r"(a[3]), "r"(b[0]), "r"(b[1]));
}

// ---------------------------------------------------------------------------
// fp16 TN GEMM via mma.sync, 2-stage cp.async double buffer.
//  A_DUAL: A has hi+lo; B_DUAL: B has hi+lo.
//  Pass set: Ahi*Bhi [+ Ahi*Blo if B_DUAL] [+ Alo*Bhi if A_DUAL]
// EPI 0: fp32 C[z*cBatch + m*ldc + n]
// EPI 1: fp32 head-major qkv: C[(z*H + (n>>6))*S*64 + m*64 + (n&63)]
// EPI 2: PV: AO fp16 single at [m*E + z*64 + n], scaled by invsum[z*S+m]
// EPI 3: score: e=exp(v) -> fp16 E (Dh); rounded partial row sums
// ---------------------------------------------------------------------------
template <int N_TILE, int EPI, bool A_DUAL, bool B_DUAL>
__global__ void __launch_bounds__(256, 1) mma_gemm(
    const __half* __restrict__ Ahi, const __half* __restrict__ Alo, long aRow, long aBatch,
    const __half* __restrict__ Bhi, const __half* __restrict__ Blo, long bRow, long bBatch,
    float* __restrict__ C, long ldc, long cBatch,
    __half* __restrict__ Dh,
    const float* __restrict__ invsum, float* __restrict__ part,
    int kChunks, int M_valid, int N_valid) {

    constexpr int AST = 80;                 // smem bytes per 32-elt row (64 + 16 pad)
    constexpr int A_BYTES = 128 * AST;
    constexpr int A_TOT = (A_DUAL ? 2 : 1) * A_BYTES;
    constexpr int B_BYTES = N_TILE * AST;
    constexpr int B_TOT = (B_DUAL ? 2 : 1) * B_BYTES;
    constexpr int STAGE = A_TOT + B_TOT;

    extern __shared__ char smem[];
    const uint32_t sb = smem_u32(smem);
    __shared__ float s_red[128];

    const int tid = threadIdx.x;
    const int wid = tid >> 5, lane = tid & 31;
    constexpr int WC = (N_TILE == 128) ? 4 : 2;
    constexpr int WM = (N_TILE == 128) ? 64 : 32;
    constexpr int WN = 32;
    constexpr int MI = WM / 16, NI = WN / 8;
    const int warpM = (wid / WC) * WM;
    const int warpN = (wid % WC) * WN;

    const int mBase = blockIdx.y * 128;
    const int nBase = blockIdx.x * N_TILE;
    const int z = blockIdx.z;
    Ahi += aBatch * z;
    if (A_DUAL) Alo += aBatch * z;
    Bhi += bBatch * z;
    if (B_DUAL) Blo += bBatch * z;

    float acc[MI][NI][4];
#pragma unroll
    for (int i = 0; i < MI; i++)
#pragma unroll
        for (int j = 0; j < NI; j++)
#pragma unroll
            for (int q = 0; q < 4; q++) acc[i][j][q] = 0.0f;

    if (EPI == 3) {
        if (tid < 128) s_red[tid] = 0.0f;
    }

    auto issue_loads = [&](int c) {
        const long k0 = (long)c * 32;
        const uint32_t st = sb + (c & 1) * STAGE;
        for (int i = tid; i < 512; i += 256) {
            const int r = i >> 2, u = i & 3;
            const int row = mBase + r;
            const int ok = (row < M_valid) ? 16 : 0;
            const long srow = (row < M_valid) ? row : (M_valid - 1);
            const long off = srow * aRow + k0 + u * 8;
            const uint32_t dst = st + r * AST + u * 16;
            cp16(dst, Ahi + off, ok);
            if constexpr (A_DUAL) cp16(dst + A_BYTES, Alo + off, ok);
        }
        for (int i = tid; i < N_TILE * 4; i += 256) {
            const int r = i >> 2, u = i & 3;
            const int row = nBase + r;
            const int ok = (row < N_valid) ? 16 : 0;
            const long srow = (row < N_valid) ? row : (N_valid - 1);
            const long off = srow * bRow + k0 + u * 8;
            const uint32_t dst = st + A_TOT + r * AST + u * 16;
            cp16(dst, Bhi + off, ok);
            if constexpr (B_DUAL) cp16(dst + B_BYTES, Blo + off, ok);
        }
        cpcommit();
    };

    issue_loads(0);

    for (int c = 0; c < kChunks; c++) {
        if (c + 1 < kChunks) { issue_loads(c + 1); cpwait<1>(); }
        else                 { cpwait<0>(); }
        __syncthreads();

        const uint32_t st = sb + (c & 1) * STAGE;
        const uint32_t aH = st, aL = st + A_BYTES;
        const uint32_t bH = st + A_TOT, bL = bH + B_BYTES;

#pragma unroll
        for (int s = 0; s < 2; s++) {
            uint32_t aHf[MI][4], aLf[MI][4], bHf[NI][2], bLf[NI][2];
            const int arow = warpM + (lane & 15);
            const uint32_t acol = s * 32 + (lane >> 4) * 16;
#pragma unroll
            for (int mi = 0; mi < MI; mi++) {
                const uint32_t ao = (uint32_t)((arow + mi * 16) * AST) + acol;
                ldm4(aHf[mi], aH + ao);
                if constexpr (A_DUAL) ldm4(aLf[mi], aL + ao);
            }
            const int l16 = lane & 15;
            const int brow = warpN + (l16 & 7);
            const uint32_t bcol = s * 32 + (l16 >> 3) * 16;
#pragma unroll
            for (int ni = 0; ni < NI; ni++) {
                const uint32_t bo = (uint32_t)((brow + ni * 8) * AST) + bcol;
                ldm2(bHf[ni], bH + bo);
                if constexpr (B_DUAL) ldm2(bLf[ni], bL + bo);
            }
#pragma unroll
            for (int mi = 0; mi < MI; mi++)
#pragma unroll
                for (int ni = 0; ni < NI; ni++) {
                    mma16816(acc[mi][ni], aHf[mi], bHf[ni]);
                    if constexpr (B_DUAL) mma16816(acc[mi][ni], aHf[mi], bLf[ni]);
                    if constexpr (A_DUAL) mma16816(acc[mi][ni], aLf[mi], bHf[ni]);
                }
        }
        __syncthreads();
    }

    // ---------------- epilogue ----------------
    if (EPI == 3) {
#pragma unroll
        for (int mi = 0; mi < MI; mi++) {
#pragma unroll
            for (int h = 0; h < 2; h++) {
                const int rl = warpM + mi * 16 + (lane >> 2) + h * 8;
                const int row = mBase + rl;
                const bool rok = (row < M_valid);
                float rsum = 0.0f;
#pragma unroll
                for (int ni = 0; ni < NI; ni++) {
                    const int col0 = nBase + warpN + ni * 8 + (lane & 3) * 2;
                    if (rok && col0 < N_valid) {
                        const float e0 = __expf(acc[mi][ni][h * 2 + 0]);
                        const float e1 = __expf(acc[mi][ni][h * 2 + 1]);
                        const __half2 hv = __floats2half2_rn(e0, e1);
                        const long o = (long)z * S_LEN * S_LEN + (long)row * S_LEN + col0;
                        *reinterpret_cast<__half2*>(Dh + o) = hv;
                        rsum += __low2float(hv) + __high2float(hv);
                    }
                }
                rsum += __shfl_xor_sync(0xFFFFFFFFu, rsum, 1);
                rsum += __shfl_xor_sync(0xFFFFFFFFu, rsum, 2);
                if ((lane & 3) == 0 && rok) atomicAdd(&s_red[rl], rsum);
            }
        }
        __syncthreads();
        if (tid < 128) {
            const int row = mBase + tid;
            if (row < M_valid)
                part[(long)blockIdx.x * (H_NUM * S_LEN) + (long)z * S_LEN + row] = s_red[tid];
        }
        return;
    }

#pragma unroll
    for (int mi = 0; mi < MI; mi++) {
#pragma unroll
        for (int ni = 0; ni < NI; ni++) {
            const int rl0 = warpM + mi * 16 + (lane >> 2);
            const int col0 = nBase + warpN + ni * 8 + (lane & 3) * 2;
#pragma unroll
            for (int h = 0; h < 2; h++) {
                const int row = mBase + rl0 + h * 8;
                if (row >= M_valid) continue;
                const float v0 = acc[mi][ni][h * 2 + 0];
                const float v1 = acc[mi][ni][h * 2 + 1];
                if (EPI == 0) {
                    if (col0 < N_valid) {
                        C[(long)z * cBatch + (long)row * ldc + col0] = v0;
                        C[(long)z * cBatch + (long)row * ldc + col0 + 1] = v1;
                    }
                } else if (EPI == 1) {
                    const long o0 = ((long)z * H_NUM + (col0 >> 6)) * S_LEN * 64 + (long)row * 64 + (col0 & 63);
                    C[o0] = v0;
                    C[o0 + 1] = v1;
                } else if (EPI == 2) {
                    const float sc = invsum[(long)z * S_LEN + row];
                    const long o = (long)row * E_DIM + (long)z * 64 + col0;
                    *reinterpret_cast<__half2*>(Dh + o) = __floats2half2_rn(v0 * sc, v1 * sc);
                }
            }
        }
    }
}

// ---------------------------------------------------------------------------
// Small kernels
// ---------------------------------------------------------------------------
// hidden -> fp16 single
__global__ void splitH_kernel(const float* __restrict__ src, __half* __restrict__ dst, long n) {
    long i = ((long)blockIdx.x * blockDim.x + threadIdx.x) * 4;
    if (i >= n) return;
    float4 v = *(const float4*)(src + i);
    __half2 a = __floats2half2_rn(v.x, v.y);
    __half2 b = __floats2half2_rn(v.z, v.w);
    *(__half2*)(dst + i) = a;
    *(__half2*)(dst + i + 2) = b;
}

// weights -> fp16 hi/lo (grid.z selects matrix)
__global__ void split4_kernel(const float* __restrict__ w0, const float* __restrict__ w1,
                              const float* __restrict__ w2, const float* __restrict__ w3,
                              __half* __restrict__ hiB, __half* __restrict__ loB) {
    const long nw = (long)E_DIM * E_DIM;
    const int z = blockIdx.z;
    const float* src = (z == 0) ? w0 : (z == 1) ? w1 : (z == 2) ? w2 : w3;
    __half* hi = hiB + (long)z * nw;
    __half* lo = loB + (long)z * nw;
    long i = ((long)blockIdx.x * blockDim.x + threadIdx.x) * 4;
    if (i >= nw) return;
    float4 v = *(const float4*)(src + i);
    float f[4] = {v.x, v.y, v.z, v.w};
#pragma unroll
    for (int j = 0; j < 4; j++) {
        __half h = __float2half_rn(f[j]);
        hi[i + j] = h;
        lo[i + j] = __float2half_rn(f[j] - __half2float(h));
    }
}

// RoPE -> fp16 single Q (scaled 1/8) and K
__global__ void rope_split_kernel(const float* __restrict__ Q, const float* __restrict__ K,
                                  const float* __restrict__ cosp, const float* __restrict__ sinp) {
    const long total = (long)H_NUM * S_LEN * 32;
    long idx = (long)blockIdx.x * blockDim.x + threadIdx.x;
    if (idx >= total) return;
    const int d = (int)(idx & 31);
    const long hs = idx >> 5;
    const int s = (int)(hs % S_LEN);
    const long base = hs << 6;

    const float c1 = cosp[s * 64 + d], s1 = sinp[s * 64 + d];
    const float c2 = cosp[s * 64 + d + 32], s2 = sinp[s * 64 + d + 32];

    float q1 = Q[base + d], q2 = Q[base + d + 32];
    float k1 = K[base + d], k2 = K[base + d + 32];

    g_Qh[base + d]      = __float2half_rn((q1 * c1 - q2 * s1) * 0.125f);
    g_Qh[base + d + 32] = __float2half_rn((q2 * c2 + q1 * s2) * 0.125f);
    g_Kh[base + d]      = __float2half_rn(k1 * c1 - k2 * s1);
    g_Kh[base + d + 32] = __float2half_rn(k2 * c2 + k1 * s2);
}

// V transpose + fp16 split: fp32 [h][s][64] -> fp16 [h][d][s] hi/lo
__global__ void vtrans_kernel(const float* __restrict__ V) {
    __shared__ float tile[64][65];
    const int h = blockIdx.z;
    const int s0 = blockIdx.x * 64;
    const int t = threadIdx.x;
    for (int i = t; i < 4096; i += 256) {
        int s = i >> 6, d = i & 63;
        tile[s][d] = V[((long)h * S_LEN + s0 + s) * 64 + d];
    }
    __syncthreads();
    for (int i = t; i < 4096; i += 256) {
        int d = i >> 6, s = i & 63;
        float v = tile[s][d];
        __half hi = __float2half_rn(v);
        long o = ((long)h * 64 + d) * S_LEN + s0 + s;
        g_Vthi[o] = hi;
        g_Vtlo[o] = __float2half_rn(v - __half2float(hi));
    }
}

__global__ void reduce_rowsum_kernel() {
    int i = blockIdx.x * blockDim.x + threadIdx.x;
    if (i >= H_NUM * S_LEN) return;
    float s = 0.f;
#pragma unroll
    for (int t = 0; t < NTILES; t++) s += g_part[t * (H_NUM * S_LEN) + i];
    g_isum[i] = 1.0f / s;
}

__global__ void normalize_kernel(float* __restrict__ W) {
    const long row = blockIdx.x;
    const float inv = g_isum[row];
    const __half* e = g_E + row * (long)S_LEN;
    float* w = W + row * (long)S_LEN;
    for (int i = threadIdx.x * 8; i < S_LEN; i += 256 * 8) {
        uint4 h4 = *(const uint4*)(e + i);
        const uint32_t hh[4] = {h4.x, h4.y, h4.z, h4.w};
        float o[8];
#pragma unroll
        for (int j = 0; j < 4; j++) {
            __half2 hb = *(const __half2*)&hh[j];
            o[j * 2 + 0] = __low2float(hb) * inv;
            o[j * 2 + 1] = __high2float(hb) * inv;
        }
        *(float4*)(w + i)     = make_float4(o[0], o[1], o[2], o[3]);
        *(float4*)(w + i + 4) = make_float4(o[4], o[5], o[6], o[7]);
    }
}

// ---------------------------------------------------------------------------
// Launch
// ---------------------------------------------------------------------------
extern "C" void kernel_launch(void* const* d_in, const int* in_sizes, int n_in,
                              void* d_out, int out_size) {
    const float* hidden = (const float*)d_in[0];
    const float* cosp   = (const float*)d_in[1];
    const float* sinp   = (const float*)d_in[2];
    const float* w[4]   = {(const float*)d_in[3], (const float*)d_in[4],
                           (const float*)d_in[5], (const float*)d_in[6]};

    float* out    = (float*)d_out;
    float* attn_w = out + (long)S_LEN * E_DIM;

    float* qkv; cudaGetSymbolAddress((void**)&qkv, g_qkv);
    __half *Hh, *Whi, *Wlo, *Qh, *Kh, *Vthi, *Vtlo, *E, *AO;
    float *part, *isum;
    cudaGetSymbolAddress((void**)&Hh, g_Hh);
    cudaGetSymbolAddress((void**)&Whi, g_Whi);  cudaGetSymbolAddress((void**)&Wlo, g_Wlo);
    cudaGetSymbolAddress((void**)&Qh, g_Qh);    cudaGetSymbolAddress((void**)&Kh, g_Kh);
    cudaGetSymbolAddress((void**)&Vthi, g_Vthi); cudaGetSymbolAddress((void**)&Vtlo, g_Vtlo);
    cudaGetSymbolAddress((void**)&E, g_E);      cudaGetSymbolAddress((void**)&AO, g_AO);
    cudaGetSymbolAddress((void**)&part, g_part); cudaGetSymbolAddress((void**)&isum, g_isum);

    static cudaStream_t s1 = nullptr;
    static cudaEvent_t evFork = nullptr, evJoin = nullptr;
    if (!s1) {
        cudaStreamCreateWithFlags(&s1, cudaStreamNonBlocking);
        cudaEventCreateWithFlags(&evFork, cudaEventDisableTiming);
        cudaEventCreateWithFlags(&evJoin, cudaEventDisableTiming);
    }

    const int SMEM_PROJ = 2 * (1 * 128 * 80 + 2 * 128 * 80);  // 61440 (A single, B dual)
    const int SMEM_SCR  = 2 * (1 * 128 * 80 + 1 * 128 * 80);  // 40960 (single/single)
    const int SMEM_PV   = 2 * (1 * 128 * 80 + 2 * 64 * 80);   // 40960 (A single, B dual)
    cudaFuncSetAttribute((const void*)mma_gemm<128, 1, false, true>,  cudaFuncAttributeMaxDynamicSharedMemorySize, SMEM_PROJ);
    cudaFuncSetAttribute((const void*)mma_gemm<128, 0, false, true>,  cudaFuncAttributeMaxDynamicSharedMemorySize, SMEM_PROJ);
    cudaFuncSetAttribute((const void*)mma_gemm<128, 3, false, false>, cudaFuncAttributeMaxDynamicSharedMemorySize, SMEM_SCR);
    cudaFuncSetAttribute((const void*)mma_gemm<64, 2, false, true>,   cudaFuncAttributeMaxDynamicSharedMemorySize, SMEM_PV);

    // 1) fp16 conversions: hidden (single), weights (hi/lo)
    {
        long n = (long)S_LEN * E_DIM;
        splitH_kernel<<<(int)((n / 4 + 255) / 256), 256>>>(hidden, Hh, n);
        long nw = (long)E_DIM * E_DIM;
        dim3 gw((unsigned)((nw / 4 + 255) / 256), 1, 4);
        split4_kernel<<<gw, 256>>>(w[0], w[1], w[2], w[3], Whi, Wlo);
    }

    // 2) QKV projections (2-pass fp16), batched over z={q,k,v}
    {
        dim3 g(E_DIM / 128, (S_LEN + 127) / 128, 3);
        mma_gemm<128, 1, false, true><<<g, 256, SMEM_PROJ>>>(
            Hh, nullptr, E_DIM, 0,
            Whi, Wlo, E_DIM, (long)E_DIM * E_DIM,
            qkv, 0, 0, nullptr, nullptr, nullptr,
            32, S_LEN, E_DIM);
    }

    // 3) RoPE -> fp16 Q (scaled), K; V transpose + fp16 split
    {
        long total = (long)H_NUM * S_LEN * 32;
        const long HSD = (long)H_NUM * S_LEN * D_DIM;
        rope_split_kernel<<<(int)((total + 255) / 256), 256>>>(qkv, qkv + HSD, cosp, sinp);
        dim3 gv(S_LEN / 64, 1, H_NUM);
        vtrans_kernel<<<gv, 256>>>(qkv + 2 * HSD);
    }

    // 4) score GEMM (1-pass fp16): E = exp(Q K^T / 8) + rounded partial sums
    {
        dim3 g((S_LEN + 127) / 128, (S_LEN + 127) / 128, H_NUM);
        mma_gemm<128, 3, false, false><<<g, 256, SMEM_SCR>>>(
            Qh, nullptr, 64, (long)S_LEN * 64,
            Kh, nullptr, 64, (long)S_LEN * 64,
            nullptr, 0, 0, E, nullptr, part,
            2, S_LEN, S_LEN);
    }

    // 5) row sums -> inverse
    reduce_rowsum_kernel<<<(H_NUM * S_LEN + 255) / 256, 256>>>();

    // 6) FORK: normalize on side stream, overlapped with PV+out
    cudaEventRecord(evFork, 0);
    cudaStreamWaitEvent(s1, evFork, 0);
    normalize_kernel<<<H_NUM * S_LEN, 256, 0, s1>>>(attn_w);
    cudaEventRecord(evJoin, s1);

    // 7) PV (2-pass fp16): E x Vt(hi/lo) -> AO fp16 single  [main stream]
    {
        dim3 g(1, (S_LEN + 127) / 128, H_NUM);
        mma_gemm<64, 2, false, true><<<g, 256, SMEM_PV>>>(
            E, nullptr, S_LEN, (long)S_LEN * S_LEN,
            Vthi, Vtlo, S_LEN, (long)64 * S_LEN,
            nullptr, 0, 0, AO, isum, nullptr,
            98, S_LEN, 64);
    }

    // 8) out = AO Wo^T (2-pass fp16)  [main stream]
    {
        dim3 g(E_DIM / 128, (S_LEN + 127) / 128, 1);
        long nw = (long)E_DIM * E_DIM;
        mma_gemm<128, 0, false, true><<<g, 256, SMEM_PROJ>>>(
            AO, nullptr, E_DIM, 0,
            Whi + 3 * nw, Wlo + 3 * nw, E_DIM, 0,
            out, E_DIM, 0, nullptr, nullptr, nullptr,
            32, S_LEN, E_DIM);
    }

    // 9) JOIN
    cudaStreamWaitEvent(0, evJoin, 0);
}

// round 10
// speedup vs baseline: 1.5074x; 1.0625x over previous
#include <cuda_runtime.h>
#include <cuda_bf16.h>
#include <cuda_fp16.h>
#include <math.h>
#include <stdint.h>

#define S_LEN 3136
#define E_DIM 1024
#define H_NUM 16
#define D_DIM 64
#define NTILES 25   // ceil(3136/128)

// ---------------------------------------------------------------------------
// Device scratch (allocation is forbidden)
// ---------------------------------------------------------------------------
__device__ float g_qkv[3][H_NUM * S_LEN * D_DIM];   // fp32 head-major q,k,v

__device__ __align__(16) __half g_Hh[S_LEN * E_DIM];            // hidden fp16 single
__device__ __align__(16) __half g_Wh[4][E_DIM * E_DIM];         // weights fp16 single
__device__ __align__(16) __half g_Qh[H_NUM * S_LEN * D_DIM];    // q fp16 single (scaled)
__device__ __align__(16) __half g_Kh[H_NUM * S_LEN * D_DIM];    // k fp16 single
__device__ __align__(16) __half g_Vthi[H_NUM * D_DIM * S_LEN];  // [h][d][s] fp16 hi
__device__ __align__(16) __half g_Vtlo[H_NUM * D_DIM * S_LEN];  // fp16 lo
__device__ __align__(16) __half g_E[(long)H_NUM * S_LEN * S_LEN]; // unnormalized exp, fp16
__device__ __align__(16) __half g_AO[S_LEN * E_DIM];            // attn out fp16 single
__device__ float g_part[NTILES * H_NUM * S_LEN];
__device__ float g_isum[H_NUM * S_LEN];

// ---------------------------------------------------------------------------
// PTX helpers
// ---------------------------------------------------------------------------
__device__ __forceinline__ uint32_t smem_u32(const void* p) {
    uint32_t a;
    asm("{ .reg .u64 t; cvta.to.shared.u64 t, %1; cvt.u32.u64 %0, t; }" : "=r"(a) : "l"(p));
    return a;
}
__device__ __forceinline__ void cp16(uint32_t dst, const void* src, int srcsize) {
    asm volatile("cp.async.cg.shared.global [%0], [%1], 16, %2;"
                 :: "r"(dst), "l"(src), "r"(srcsize));
}
__device__ __forceinline__ void cpcommit() { asm volatile("cp.async.commit_group;"); }
template <int N> __device__ __forceinline__ void cpwait() {
    asm volatile("cp.async.wait_group %0;" :: "n"(N));
}
__device__ __forceinline__ void ldm4(uint32_t* r, uint32_t a) {
    asm volatile("ldmatrix.sync.aligned.m8n8.x4.shared.b16 {%0,%1,%2,%3}, [%4];"
                 : "=r"(r[0]), "=r"(r[1]), "=r"(r[2]), "=r"(r[3]) : "r"(a));
}
__device__ __forceinline__ void ldm2(uint32_t* r, uint32_t a) {
    asm volatile("ldmatrix.sync.aligned.m8n8.x2.shared.b16 {%0,%1}, [%2];"
                 : "=r"(r[0]), "=r"(r[1]) : "r"(a));
}
__device__ __forceinline__ void mma16816(float* d, const uint32_t* a, const uint32_t* b) {
    asm volatile("mma.sync.aligned.m16n8k16.row.col.f32.f16.f16.f32 "
                 "{%0,%1,%2,%3}, {%4,%5,%6,%7}, {%8,%9}, {%0,%1,%2,%3};"
                 : "+f"(d[0]), "+f"(d[1]), "+f"(d[2]), "+f"(d[3])
                 : "r"(a[0]), "r"(a[1]), "r"(a[2]), "r"(a[3]), "r"(b[0]), "r"(b[1]));
}

// ---------------------------------------------------------------------------
// fp16 TN GEMM via mma.sync, 2-stage cp.async double buffer.
//  A_DUAL: A has hi+lo; B_DUAL: B has hi+lo.
//  Pass set: Ahi*Bhi [+ Ahi*Blo if B_DUAL] [+ Alo*Bhi if A_DUAL]
// EPI 0: fp32 C[z*cBatch + m*ldc + n]
// EPI 1: fp32 head-major qkv: C[(z*H + (n>>6))*S*64 + m*64 + (n&63)]
// EPI 2: PV: AO fp16 single at [m*E + z*64 + n], scaled by invsum[z*S+m]
// EPI 3: score: e=exp(v) -> fp16 E (Dh); rounded partial row sums
// ---------------------------------------------------------------------------
template <int N_TILE, int EPI, bool A_DUAL, bool B_DUAL>
__global__ void __launch_bounds__(256, 1) mma_gemm(
    const __half* __restrict__ Ahi, const __half* __restrict__ Alo, long aRow, long aBatch,
    const __half* __restrict__ Bhi, const __half* __restrict__ Blo, long bRow, long bBatch,
    float* __restrict__ C, long ldc, long cBatch,
    __half* __restrict__ Dh,
    const float* __restrict__ invsum, float* __restrict__ part,
    int kChunks, int M_valid, int N_valid) {

    constexpr int AST = 80;                 // smem bytes per 32-elt row (64 + 16 pad)
    constexpr int A_BYTES = 128 * AST;
    constexpr int A_TOT = (A_DUAL ? 2 : 1) * A_BYTES;
    constexpr int B_BYTES = N_TILE * AST;
    constexpr int B_TOT = (B_DUAL ? 2 : 1) * B_BYTES;
    constexpr int STAGE = A_TOT + B_TOT;

    extern __shared__ char smem[];
    const uint32_t sb = smem_u32(smem);
    __shared__ float s_red[128];

    const int tid = threadIdx.x;
    const int wid = tid >> 5, lane = tid & 31;
    constexpr int WC = (N_TILE == 128) ? 4 : 2;
    constexpr int WM = (N_TILE == 128) ? 64 : 32;
    constexpr int WN = 32;
    constexpr int MI = WM / 16, NI = WN / 8;
    const int warpM = (wid / WC) * WM;
    const int warpN = (wid % WC) * WN;

    const int mBase = blockIdx.y * 128;
    const int nBase = blockIdx.x * N_TILE;
    const int z = blockIdx.z;
    Ahi += aBatch * z;
    if (A_DUAL) Alo += aBatch * z;
    Bhi += bBatch * z;
    if (B_DUAL) Blo += bBatch * z;

    float acc[MI][NI][4];
#pragma unroll
    for (int i = 0; i < MI; i++)
#pragma unroll
        for (int j = 0; j < NI; j++)
#pragma unroll
            for (int q = 0; q < 4; q++) acc[i][j][q] = 0.0f;

    if (EPI == 3) {
        if (tid < 128) s_red[tid] = 0.0f;
    }

    auto issue_loads = [&](int c) {
        const long k0 = (long)c * 32;
        const uint32_t st = sb + (c & 1) * STAGE;
        for (int i = tid; i < 512; i += 256) {
            const int r = i >> 2, u = i & 3;
            const int row = mBase + r;
            const int ok = (row < M_valid) ? 16 : 0;
            const long srow = (row < M_valid) ? row : (M_valid - 1);
            const long off = srow * aRow + k0 + u * 8;
            const uint32_t dst = st + r * AST + u * 16;
            cp16(dst, Ahi + off, ok);
            if constexpr (A_DUAL) cp16(dst + A_BYTES, Alo + off, ok);
        }
        for (int i = tid; i < N_TILE * 4; i += 256) {
            const int r = i >> 2, u = i & 3;
            const int row = nBase + r;
            const int ok = (row < N_valid) ? 16 : 0;
            const long srow = (row < N_valid) ? row : (N_valid - 1);
            const long off = srow * bRow + k0 + u * 8;
            const uint32_t dst = st + A_TOT + r * AST + u * 16;
            cp16(dst, Bhi + off, ok);
            if constexpr (B_DUAL) cp16(dst + B_BYTES, Blo + off, ok);
        }
        cpcommit();
    };

    issue_loads(0);

    for (int c = 0; c < kChunks; c++) {
        if (c + 1 < kChunks) { issue_loads(c + 1); cpwait<1>(); }
        else                 { cpwait<0>(); }
        __syncthreads();

        const uint32_t st = sb + (c & 1) * STAGE;
        const uint32_t aH = st, aL = st + A_BYTES;
        const uint32_t bH = st + A_TOT, bL = bH + B_BYTES;

#pragma unroll
        for (int s = 0; s < 2; s++) {
            uint32_t aHf[MI][4], aLf[MI][4], bHf[NI][2], bLf[NI][2];
            const int arow = warpM + (lane & 15);
            const uint32_t acol = s * 32 + (lane >> 4) * 16;
#pragma unroll
            for (int mi = 0; mi < MI; mi++) {
                const uint32_t ao = (uint32_t)((arow + mi * 16) * AST) + acol;
                ldm4(aHf[mi], aH + ao);
                if constexpr (A_DUAL) ldm4(aLf[mi], aL + ao);
            }
            const int l16 = lane & 15;
            const int brow = warpN + (l16 & 7);
            const uint32_t bcol = s * 32 + (l16 >> 3) * 16;
#pragma unroll
            for (int ni = 0; ni < NI; ni++) {
                const uint32_t bo = (uint32_t)((brow + ni * 8) * AST) + bcol;
                ldm2(bHf[ni], bH + bo);
                if constexpr (B_DUAL) ldm2(bLf[ni], bL + bo);
            }
#pragma unroll
            for (int mi = 0; mi < MI; mi++)
#pragma unroll
                for (int ni = 0; ni < NI; ni++) {
                    mma16816(acc[mi][ni], aHf[mi], bHf[ni]);
                    if constexpr (B_DUAL) mma16816(acc[mi][ni], aHf[mi], bLf[ni]);
                    if constexpr (A_DUAL) mma16816(acc[mi][ni], aLf[mi], bHf[ni]);
                }
        }
        __syncthreads();
    }

    // ---------------- epilogue ----------------
    if (EPI == 3) {
#pragma unroll
        for (int mi = 0; mi < MI; mi++) {
#pragma unroll
            for (int h = 0; h < 2; h++) {
                const int rl = warpM + mi * 16 + (lane >> 2) + h * 8;
                const int row = mBase + rl;
                const bool rok = (row < M_valid);
                float rsum = 0.0f;
#pragma unroll
                for (int ni = 0; ni < NI; ni++) {
                    const int col0 = nBase + warpN + ni * 8 + (lane & 3) * 2;
                    if (rok && col0 < N_valid) {
                        const float e0 = __expf(acc[mi][ni][h * 2 + 0]);
                        const float e1 = __expf(acc[mi][ni][h * 2 + 1]);
                        const __half2 hv = __floats2half2_rn(e0, e1);
                        const long o = (long)z * S_LEN * S_LEN + (long)row * S_LEN + col0;
                        *reinterpret_cast<__half2*>(Dh + o) = hv;
                        rsum += __low2float(hv) + __high2float(hv);
                    }
                }
                rsum += __shfl_xor_sync(0xFFFFFFFFu, rsum, 1);
                rsum += __shfl_xor_sync(0xFFFFFFFFu, rsum, 2);
                if ((lane & 3) == 0 && rok) atomicAdd(&s_red[rl], rsum);
            }
        }
        __syncthreads();
        if (tid < 128) {
            const int row = mBase + tid;
            if (row < M_valid)
                part[(long)blockIdx.x * (H_NUM * S_LEN) + (long)z * S_LEN + row] = s_red[tid];
        }
        return;
    }

#pragma unroll
    for (int mi = 0; mi < MI; mi++) {
#pragma unroll
        for (int ni = 0; ni < NI; ni++) {
            const int rl0 = warpM + mi * 16 + (lane >> 2);
            const int col0 = nBase + warpN + ni * 8 + (lane & 3) * 2;
#pragma unroll
            for (int h = 0; h < 2; h++) {
                const int row = mBase + rl0 + h * 8;
                if (row >= M_valid) continue;
                const float v0 = acc[mi][ni][h * 2 + 0];
                const float v1 = acc[mi][ni][h * 2 + 1];
                if (EPI == 0) {
                    if (col0 < N_valid) {
                        C[(long)z * cBatch + (long)row * ldc + col0] = v0;
                        C[(long)z * cBatch + (long)row * ldc + col0 + 1] = v1;
                    }
                } else if (EPI == 1) {
                    const long o0 = ((long)z * H_NUM + (col0 >> 6)) * S_LEN * 64 + (long)row * 64 + (col0 & 63);
                    C[o0] = v0;
                    C[o0 + 1] = v1;
                } else if (EPI == 2) {
                    const float sc = invsum[(long)z * S_LEN + row];
                    const long o = (long)row * E_DIM + (long)z * 64 + col0;
                    *reinterpret_cast<__half2*>(Dh + o) = __floats2half2_rn(v0 * sc, v1 * sc);
                }
            }
        }
    }
}

// ---------------------------------------------------------------------------
// Small kernels
// ---------------------------------------------------------------------------
__global__ void splitH_kernel(const float* __restrict__ src, __half* __restrict__ dst, long n) {
    long i = ((long)blockIdx.x * blockDim.x + threadIdx.x) * 4;
    if (i >= n) return;
    float4 v = *(const float4*)(src + i);
    *(__half2*)(dst + i)     = __floats2half2_rn(v.x, v.y);
    *(__half2*)(dst + i + 2) = __floats2half2_rn(v.z, v.w);
}

// weights -> fp16 single (grid.z selects matrix)
__global__ void splitW4_kernel(const float* __restrict__ w0, const float* __restrict__ w1,
                               const float* __restrict__ w2, const float* __restrict__ w3,
                               __half* __restrict__ dstB) {
    const long nw = (long)E_DIM * E_DIM;
    const int z = blockIdx.z;
    const float* src = (z == 0) ? w0 : (z == 1) ? w1 : (z == 2) ? w2 : w3;
    __half* dst = dstB + (long)z * nw;
    long i = ((long)blockIdx.x * blockDim.x + threadIdx.x) * 4;
    if (i >= nw) return;
    float4 v = *(const float4*)(src + i);
    *(__half2*)(dst + i)     = __floats2half2_rn(v.x, v.y);
    *(__half2*)(dst + i + 2) = __floats2half2_rn(v.z, v.w);
}

__global__ void rope_split_kernel(const float* __restrict__ Q, const float* __restrict__ K,
                                  const float* __restrict__ cosp, const float* __restrict__ sinp) {
    const long total = (long)H_NUM * S_LEN * 32;
    long idx = (long)blockIdx.x * blockDim.x + threadIdx.x;
    if (idx >= total) return;
    const int d = (int)(idx & 31);
    const long hs = idx >> 5;
    const int s = (int)(hs % S_LEN);
    const long base = hs << 6;

    const float c1 = cosp[s * 64 + d], s1 = sinp[s * 64 + d];
    const float c2 = cosp[s * 64 + d + 32], s2 = sinp[s * 64 + d + 32];

    float q1 = Q[base + d], q2 = Q[base + d + 32];
    float k1 = K[base + d], k2 = K[base + d + 32];

    g_Qh[base + d]      = __float2half_rn((q1 * c1 - q2 * s1) * 0.125f);
    g_Qh[base + d + 32] = __float2half_rn((q2 * c2 + q1 * s2) * 0.125f);
    g_Kh[base + d]      = __float2half_rn(k1 * c1 - k2 * s1);
    g_Kh[base + d + 32] = __float2half_rn(k2 * c2 + k1 * s2);
}

__global__ void vtrans_kernel(const float* __restrict__ V) {
    __shared__ float tile[64][65];
    const int h = blockIdx.z;
    const int s0 = blockIdx.x * 64;
    const int t = threadIdx.x;
    for (int i = t; i < 4096; i += 256) {
        int s = i >> 6, d = i & 63;
        tile[s][d] = V[((long)h * S_LEN + s0 + s) * 64 + d];
    }
    __syncthreads();
    for (int i = t; i < 4096; i += 256) {
        int d = i >> 6, s = i & 63;
        float v = tile[s][d];
        __half hi = __float2half_rn(v);
        long o = ((long)h * 64 + d) * S_LEN + s0 + s;
        g_Vthi[o] = hi;
        g_Vtlo[o] = __float2half_rn(v - __half2float(hi));
    }
}

__global__ void reduce_rowsum_kernel() {
    int i = blockIdx.x * blockDim.x + threadIdx.x;
    if (i >= H_NUM * S_LEN) return;
    float s = 0.f;
#pragma unroll
    for (int t = 0; t < NTILES; t++) s += g_part[t * (H_NUM * S_LEN) + i];
    g_isum[i] = 1.0f / s;
}

__global__ void normalize_kernel(float* __restrict__ W) {
    const long row = blockIdx.x;
    const float inv = g_isum[row];
    const __half* e = g_E + row * (long)S_LEN;
    float* w = W + row * (long)S_LEN;
    for (int i = threadIdx.x * 8; i < S_LEN; i += 256 * 8) {
        uint4 h4 = *(const uint4*)(e + i);
        const uint32_t hh[4] = {h4.x, h4.y, h4.z, h4.w};
        float o[8];
#pragma unroll
        for (int j = 0; j < 4; j++) {
            __half2 hb = *(const __half2*)&hh[j];
            o[j * 2 + 0] = __low2float(hb) * inv;
            o[j * 2 + 1] = __high2float(hb) * inv;
        }
        *(float4*)(w + i)     = make_float4(o[0], o[1], o[2], o[3]);
        *(float4*)(w + i + 4) = make_float4(o[4], o[5], o[6], o[7]);
    }
}

// ---------------------------------------------------------------------------
// Launch
// ---------------------------------------------------------------------------
extern "C" void kernel_launch(void* const* d_in, const int* in_sizes, int n_in,
                              void* d_out, int out_size) {
    const float* hidden = (const float*)d_in[0];
    const float* cosp   = (const float*)d_in[1];
    const float* sinp   = (const float*)d_in[2];
    const float* w[4]   = {(const float*)d_in[3], (const float*)d_in[4],
                           (const float*)d_in[5], (const float*)d_in[6]};

    float* out    = (float*)d_out;
    float* attn_w = out + (long)S_LEN * E_DIM;

    float* qkv; cudaGetSymbolAddress((void**)&qkv, g_qkv);
    __half *Hh, *Wh, *Qh, *Kh, *Vthi, *Vtlo, *E, *AO;
    float *part, *isum;
    cudaGetSymbolAddress((void**)&Hh, g_Hh);
    cudaGetSymbolAddress((void**)&Wh, g_Wh);
    cudaGetSymbolAddress((void**)&Qh, g_Qh);    cudaGetSymbolAddress((void**)&Kh, g_Kh);
    cudaGetSymbolAddress((void**)&Vthi, g_Vthi); cudaGetSymbolAddress((void**)&Vtlo, g_Vtlo);
    cudaGetSymbolAddress((void**)&E, g_E);      cudaGetSymbolAddress((void**)&AO, g_AO);
    cudaGetSymbolAddress((void**)&part, g_part); cudaGetSymbolAddress((void**)&isum, g_isum);

    static cudaStream_t s1 = nullptr;
    static cudaEvent_t evFork = nullptr, evJoin = nullptr;
    if (!s1) {
        cudaStreamCreateWithFlags(&s1, cudaStreamNonBlocking);
        cudaEventCreateWithFlags(&evFork, cudaEventDisableTiming);
        cudaEventCreateWithFlags(&evJoin, cudaEventDisableTiming);
    }

    const int SMEM_PROJ = 2 * (1 * 128 * 80 + 1 * 128 * 80);  // 40960 (single/single)
    const int SMEM_SCR  = 2 * (1 * 128 * 80 + 1 * 128 * 80);  // 40960
    const int SMEM_PV   = 2 * (1 * 128 * 80 + 2 * 64 * 80);   // 40960 (A single, B dual)
    cudaFuncSetAttribute((const void*)mma_gemm<128, 1, false, false>, cudaFuncAttributeMaxDynamicSharedMemorySize, SMEM_PROJ);
    cudaFuncSetAttribute((const void*)mma_gemm<128, 0, false, false>, cudaFuncAttributeMaxDynamicSharedMemorySize, SMEM_PROJ);
    cudaFuncSetAttribute((const void*)mma_gemm<128, 3, false, false>, cudaFuncAttributeMaxDynamicSharedMemorySize, SMEM_SCR);
    cudaFuncSetAttribute((const void*)mma_gemm<64, 2, false, true>,   cudaFuncAttributeMaxDynamicSharedMemorySize, SMEM_PV);

    // 1) fp16 conversions: hidden (single), weights (single)
    {
        long n = (long)S_LEN * E_DIM;
        splitH_kernel<<<(int)((n / 4 + 255) / 256), 256>>>(hidden, Hh, n);
        long nw = (long)E_DIM * E_DIM;
        dim3 gw((unsigned)((nw / 4 + 255) / 256), 1, 4);
        splitW4_kernel<<<gw, 256>>>(w[0], w[1], w[2], w[3], Wh);
    }

    // 2) QKV projections (1-pass fp16), batched over z={q,k,v}
    {
        dim3 g(E_DIM / 128, (S_LEN + 127) / 128, 3);
        mma_gemm<128, 1, false, false><<<g, 256, SMEM_PROJ>>>(
            Hh, nullptr, E_DIM, 0,
            Wh, nullptr, E_DIM, (long)E_DIM * E_DIM,
            qkv, 0, 0, nullptr, nullptr, nullptr,
            32, S_LEN, E_DIM);
    }

    // 3) RoPE -> fp16 Q (scaled), K; V transpose + fp16 split
    {
        long total = (long)H_NUM * S_LEN * 32;
        const long HSD = (long)H_NUM * S_LEN * D_DIM;
        rope_split_kernel<<<(int)((total + 255) / 256), 256>>>(qkv, qkv + HSD, cosp, sinp);
        dim3 gv(S_LEN / 64, 1, H_NUM);
        vtrans_kernel<<<gv, 256>>>(qkv + 2 * HSD);
    }

    // 4) score GEMM (1-pass fp16): E = exp(Q K^T / 8) + rounded partial sums
    {
        dim3 g((S_LEN + 127) / 128, (S_LEN + 127) / 128, H_NUM);
        mma_gemm<128, 3, false, false><<<g, 256, SMEM_SCR>>>(
            Qh, nullptr, 64, (long)S_LEN * 64,
            Kh, nullptr, 64, (long)S_LEN * 64,
            nullptr, 0, 0, E, nullptr, part,
            2, S_LEN, S_LEN);
    }

    // 5) row sums -> inverse
    reduce_rowsum_kernel<<<(H_NUM * S_LEN + 255) / 256, 256>>>();

    // 6) FORK: normalize on side stream, overlapped with PV+out
    cudaEventRecord(evFork, 0);
    cudaStreamWaitEvent(s1, evFork, 0);
    normalize_kernel<<<H_NUM * S_LEN, 256, 0, s1>>>(attn_w);
    cudaEventRecord(evJoin, s1);

    // 7) PV (2-pass fp16): E x Vt(hi/lo) -> AO fp16 single  [main stream]
    {
        dim3 g(1, (S_LEN + 127) / 128, H_NUM);
        mma_gemm<64, 2, false, true><<<g, 256, SMEM_PV>>>(
            E, nullptr, S_LEN, (long)S_LEN * S_LEN,
            Vthi, Vtlo, S_LEN, (long)64 * S_LEN,
            nullptr, 0, 0, AO, isum, nullptr,
            98, S_LEN, 64);
    }

    // 8) out = AO Wo^T (1-pass fp16)  [main stream]
    {
        dim3 g(E_DIM / 128, (S_LEN + 127) / 128, 1);
        long nw = (long)E_DIM * E_DIM;
        mma_gemm<128, 0, false, false><<<g, 256, SMEM_PROJ>>>(
            AO, nullptr, E_DIM, 0,
            Wh + 3 * nw, nullptr, E_DIM, 0,
            out, E_DIM, 0, nullptr, nullptr, nullptr,
            32, S_LEN, E_DIM);
    }

    // 9) JOIN
    cudaStreamWaitEvent(0, evJoin, 0);
}

// round 11
// speedup vs baseline: 1.8643x; 1.2367x over previous
#include <cuda_runtime.h>
#include <cuda_fp16.h>
#include <math.h>
#include <stdint.h>

#define S_LEN 3136
#define E_DIM 1024
#define H_NUM 16
#define D_DIM 64

// ---------------------------------------------------------------------------
// Device scratch (allocation is forbidden)
// ---------------------------------------------------------------------------
__device__ float g_qkv[3][H_NUM * S_LEN * D_DIM];   // fp32 head-major q,k,v

__device__ __align__(16) __half g_Hh[S_LEN * E_DIM];            // hidden fp16
__device__ __align__(16) __half g_Wh[4][E_DIM * E_DIM];         // weights fp16
__device__ __align__(16) __half g_Qh[H_NUM * S_LEN * D_DIM];    // q fp16 (scaled 1/8)
__device__ __align__(16) __half g_Kh[H_NUM * S_LEN * D_DIM];    // k fp16
__device__ __align__(16) __half g_Vthi[H_NUM * D_DIM * S_LEN];  // [h][d][s] fp16 hi
__device__ __align__(16) __half g_Vtlo[H_NUM * D_DIM * S_LEN];  // fp16 lo
__device__ __align__(16) __half g_E[(long)H_NUM * S_LEN * S_LEN]; // unnormalized exp
__device__ __align__(16) __half g_AO[S_LEN * E_DIM];            // normalized attn out
__device__ float g_isum[H_NUM * S_LEN];                         // 1 / rowsum

// ---------------------------------------------------------------------------
// PTX helpers
// ---------------------------------------------------------------------------
__device__ __forceinline__ uint32_t smem_u32(const void* p) {
    uint32_t a;
    asm("{ .reg .u64 t; cvta.to.shared.u64 t, %1; cvt.u32.u64 %0, t; }" : "=r"(a) : "l"(p));
    return a;
}
__device__ __forceinline__ void cp16(uint32_t dst, const void* src, int srcsize) {
    asm volatile("cp.async.cg.shared.global [%0], [%1], 16, %2;"
                 :: "r"(dst), "l"(src), "r"(srcsize));
}
__device__ __forceinline__ void cpcommit() { asm volatile("cp.async.commit_group;"); }
template <int N> __device__ __forceinline__ void cpwait() {
    asm volatile("cp.async.wait_group %0;" :: "n"(N));
}
__device__ __forceinline__ void ldm4(uint32_t* r, uint32_t a) {
    asm volatile("ldmatrix.sync.aligned.m8n8.x4.shared.b16 {%0,%1,%2,%3}, [%4];"
                 : "=r"(r[0]), "=r"(r[1]), "=r"(r[2]), "=r"(r[3]) : "r"(a));
}
__device__ __forceinline__ void ldm2(uint32_t* r, uint32_t a) {
    asm volatile("ldmatrix.sync.aligned.m8n8.x2.shared.b16 {%0,%1}, [%2];"
                 : "=r"(r[0]), "=r"(r[1]) : "r"(a));
}
__device__ __forceinline__ void mma16816(float* d, const uint32_t* a, const uint32_t* b) {
    asm volatile("mma.sync.aligned.m16n8k16.row.col.f32.f16.f16.f32 "
                 "{%0,%1,%2,%3}, {%4,%5,%6,%7}, {%8,%9}, {%0,%1,%2,%3};"
                 : "+f"(d[0]), "+f"(d[1]), "+f"(d[2]), "+f"(d[3])
                 : "r"(a[0]), "r"(a[1]), "r"(a[2]), "r"(a[3]), "r"(b[0]), "r"(b[1]));
}

// ---------------------------------------------------------------------------
// fp16 single/single TN GEMM (proven core) for QKV-proj and out-proj.
// EPI 0: fp32 C[z*cBatch + m*ldc + n]
// EPI 1: fp32 head-major qkv: C[(z*H + (n>>6))*S*64 + m*64 + (n&63)]
// ---------------------------------------------------------------------------
template <int EPI>
__global__ void __launch_bounds__(256, 1) mma_gemm(
    const __half* __restrict__ A, long aRow,
    const __half* __restrict__ B, long bRow, long bBatch,
    float* __restrict__ C, long ldc, long cBatch,
    int kChunks, int M_valid) {

    constexpr int AST = 80;
    constexpr int A_BYTES = 128 * AST;
    constexpr int B_BYTES = 128 * AST;
    constexpr int STAGE = A_BYTES + B_BYTES;

    extern __shared__ char smem[];
    const uint32_t sb = smem_u32(smem);

    const int tid = threadIdx.x;
    const int wid = tid >> 5, lane = tid & 31;
    const int warpM = (wid / 4) * 64;
    const int warpN = (wid % 4) * 32;

    const int mBase = blockIdx.y * 128;
    const int nBase = blockIdx.x * 128;
    const int z = blockIdx.z;
    B += bBatch * z;

    float acc[4][4][4];
#pragma unroll
    for (int i = 0; i < 4; i++)
#pragma unroll
        for (int j = 0; j < 4; j++)
#pragma unroll
            for (int q = 0; q < 4; q++) acc[i][j][q] = 0.0f;

    auto issue_loads = [&](int c) {
        const long k0 = (long)c * 32;
        const uint32_t st = sb + (c & 1) * STAGE;
        for (int i = tid; i < 512; i += 256) {
            const int r = i >> 2, u = i & 3;
            const int row = mBase + r;
            const int ok = (row < M_valid) ? 16 : 0;
            const long srow = (row < M_valid) ? row : (M_valid - 1);
            cp16(st + r * AST + u * 16, A + srow * aRow + k0 + u * 8, ok);
        }
        for (int i = tid; i < 512; i += 256) {
            const int r = i >> 2, u = i & 3;
            cp16(st + A_BYTES + r * AST + u * 16, B + (long)(nBase + r) * bRow + k0 + u * 8, 16);
        }
        cpcommit();
    };

    issue_loads(0);

    for (int c = 0; c < kChunks; c++) {
        if (c + 1 < kChunks) { issue_loads(c + 1); cpwait<1>(); }
        else                 { cpwait<0>(); }
        __syncthreads();

        const uint32_t st = sb + (c & 1) * STAGE;
        const uint32_t aB = st, bB = st + A_BYTES;

#pragma unroll
        for (int s = 0; s < 2; s++) {
            uint32_t af[4][4], bf[4][2];
            const int arow = warpM + (lane & 15);
            const uint32_t acol = s * 32 + (lane >> 4) * 16;
#pragma unroll
            for (int mi = 0; mi < 4; mi++)
                ldm4(af[mi], aB + (uint32_t)((arow + mi * 16) * AST) + acol);
            const int l16 = lane & 15;
            const int brow = warpN + (l16 & 7);
            const uint32_t bcol = s * 32 + (l16 >> 3) * 16;
#pragma unroll
            for (int ni = 0; ni < 4; ni++)
                ldm2(bf[ni], bB + (uint32_t)((brow + ni * 8) * AST) + bcol);
#pragma unroll
            for (int mi = 0; mi < 4; mi++)
#pragma unroll
                for (int ni = 0; ni < 4; ni++)
                    mma16816(acc[mi][ni], af[mi], bf[ni]);
        }
        __syncthreads();
    }

#pragma unroll
    for (int mi = 0; mi < 4; mi++) {
#pragma unroll
        for (int ni = 0; ni < 4; ni++) {
            const int rl0 = warpM + mi * 16 + (lane >> 2);
            const int col0 = nBase + warpN + ni * 8 + (lane & 3) * 2;
#pragma unroll
            for (int h = 0; h < 2; h++) {
                const int row = mBase + rl0 + h * 8;
                if (row >= M_valid) continue;
                const float v0 = acc[mi][ni][h * 2 + 0];
                const float v1 = acc[mi][ni][h * 2 + 1];
                if (EPI == 0) {
                    C[(long)z * cBatch + (long)row * ldc + col0] = v0;
                    C[(long)z * cBatch + (long)row * ldc + col0 + 1] = v1;
                } else {
                    const long o0 = ((long)z * H_NUM + (col0 >> 6)) * S_LEN * 64 + (long)row * 64 + (col0 & 63);
                    C[o0] = v0;
                    C[o0 + 1] = v1;
                }
            }
        }
    }
}

// ---------------------------------------------------------------------------
// Fused attention: per (m-tile 128, head) CTA, loop 25 K/V tiles:
//   S = Q Kt (MMA) -> exp -> write fp16 E + rowsum in regs -> pack P frags
//   -> AO_acc += P * V (hi + lo MMAs). Finalize: AO *= 1/rowsum, write isum.
// ---------------------------------------------------------------------------
__global__ void __launch_bounds__(256, 1) fused_attn(
    const __half* __restrict__ Qh, const __half* __restrict__ Kh,
    const __half* __restrict__ Vhi, const __half* __restrict__ Vlo,
    __half* __restrict__ E, __half* __restrict__ AO, float* __restrict__ isum) {

    constexpr int QK_ST = 176;                    // 64 halves + pad (conflict-free)
    constexpr int V_ST  = 272;                    // 128 halves + pad
    constexpr int Q_BYTES = 128 * QK_ST;          // 22528
    constexpr int K_BYTES = 128 * QK_ST;          // 22528
    constexpr int V_BYTES = 64 * V_ST;            // 17408
    constexpr int STAGE = K_BYTES + 2 * V_BYTES;  // 57344
    constexpr int NT = 25;                        // ceil(S/128)

    extern __shared__ char smem[];
    const uint32_t sb = smem_u32(smem);
    const uint32_t qb = sb;
    const uint32_t stb = sb + Q_BYTES;

    const int tid = threadIdx.x;
    const int w = tid >> 5, lane = tid & 31;
    const int h = blockIdx.y;
    const int mBase = blockIdx.x * 128;
    const long hS = (long)h * S_LEN;

    // ---- issue Q tile + KV stage 0 (one group), then KV stage 1 ----
    for (int i = tid; i < 1024; i += 256) {
        const int r = i >> 3, u = i & 7;
        const int row = mBase + r;
        const int ok = (row < S_LEN) ? 16 : 0;
        const long srow = (row < S_LEN) ? row : (S_LEN - 1);
        cp16(qb + r * QK_ST + u * 16, Qh + (hS + srow) * 64 + u * 8, ok);
    }
    auto issue_kv = [&](int t) {
        const int kBase = t * 128;
        const uint32_t st = stb + (t & 1) * STAGE;
        for (int i = tid; i < 1024; i += 256) {
            const int r = i >> 3, u = i & 7;
            const int row = kBase + r;
            const int ok = (row < S_LEN) ? 16 : 0;
            const long srow = (row < S_LEN) ? row : (S_LEN - 1);
            cp16(st + r * QK_ST + u * 16, Kh + (hS + srow) * 64 + u * 8, ok);
        }
        for (int i = tid; i < 1024; i += 256) {
            const int r = i >> 4, u = i & 15;     // r: d-row 0..63, u: 8-half col group
            const int col = kBase + u * 8;
            const int ok = (col < S_LEN) ? 16 : 0;
            const long scol = (col < S_LEN) ? col : (S_LEN - 8);
            const long off = ((long)h * 64 + r) * S_LEN + scol;
            const uint32_t dst = st + K_BYTES + r * V_ST + u * 16;
            cp16(dst, Vhi + off, ok);
            cp16(dst + V_BYTES, Vlo + off, ok);
        }
        cpcommit();
    };
    issue_kv(0);               // commits Q + stage0 together
    issue_kv(1);
    cpwait<1>();               // Q + stage0 ready
    __syncthreads();

    // ---- Q fragments (held in registers all kernel) ----
    uint32_t qf[4][4];
    {
        const int arow = w * 16 + (lane & 15);
        const uint32_t acol = (uint32_t)((lane >> 4) * 16);
#pragma unroll
        for (int ks = 0; ks < 4; ks++)
            ldm4(qf[ks], qb + (uint32_t)(arow * QK_ST) + ks * 32 + acol);
    }

    float acc_o[8][4];
#pragma unroll
    for (int i = 0; i < 8; i++)
#pragma unroll
        for (int q = 0; q < 4; q++) acc_o[i][q] = 0.0f;
    float rsum0 = 0.0f, rsum1 = 0.0f;

    const int row0 = mBase + w * 16 + (lane >> 2);
    const int row1 = row0 + 8;
    const int l16 = lane & 15;
    const int brow_off = l16 & 7;
    const uint32_t bcol_off = (uint32_t)((l16 >> 3) * 16);

    for (int t = 0; t < NT; t++) {
        const uint32_t st = stb + (t & 1) * STAGE;
        const int kBase = t * 128;

        // ---- score MMAs: acc[ni] (16 rows x 128 cols per warp) ----
        float acc[16][4];
#pragma unroll
        for (int i = 0; i < 16; i++)
#pragma unroll
            for (int q = 0; q < 4; q++) acc[i][q] = 0.0f;
#pragma unroll
        for (int ks = 0; ks < 4; ks++) {
#pragma unroll
            for (int ni = 0; ni < 16; ni++) {
                uint32_t b[2];
                ldm2(b, st + (uint32_t)((ni * 8 + brow_off) * QK_ST) + ks * 32 + bcol_off);
                mma16816(acc[ni], qf[ks], b);
            }
        }

        // ---- exp + E write + rowsum + pack P fragments ----
        uint32_t eh[32];
#pragma unroll
        for (int ni = 0; ni < 16; ni++) {
            const int col0 = kBase + ni * 8 + (lane & 3) * 2;
            float e00 = 0.f, e01 = 0.f, e10 = 0.f, e11 = 0.f;
            if (col0 < S_LEN) {
                e00 = __expf(acc[ni][0]); e01 = __expf(acc[ni][1]);
                e10 = __expf(acc[ni][2]); e11 = __expf(acc[ni][3]);
            }
            const __half2 hv0 = __floats2half2_rn(e00, e01);
            const __half2 hv1 = __floats2half2_rn(e10, e11);
            eh[ni * 2]     = *(const uint32_t*)&hv0;
            eh[ni * 2 + 1] = *(const uint32_t*)&hv1;
            if (col0 < S_LEN) {
                if (row0 < S_LEN) *reinterpret_cast<__half2*>(E + (hS + row0) * S_LEN + col0) = hv0;
                if (row1 < S_LEN) *reinterpret_cast<__half2*>(E + (hS + row1) * S_LEN + col0) = hv1;
                rsum0 += __low2float(hv0) + __high2float(hv0);
                rsum1 += __low2float(hv1) + __high2float(hv1);
            }
        }

        // ---- PV MMAs: acc_o += P * Vhi + P * Vlo ----
#pragma unroll
        for (int ks = 0; ks < 8; ks++) {
#pragma unroll
            for (int ni = 0; ni < 8; ni++) {
                uint32_t b[2];
                const uint32_t va = st + K_BYTES + (uint32_t)((ni * 8 + brow_off) * V_ST) + ks * 32 + bcol_off;
                ldm2(b, va);
                mma16816(acc_o[ni], &eh[ks * 4], b);
                ldm2(b, va + V_BYTES);
                mma16816(acc_o[ni], &eh[ks * 4], b);
            }
        }

        __syncthreads();                         // all warps done reading buffer t&1
        if (t + 2 < NT) issue_kv(t + 2);         // refill buffer t&1
        if (t + 1 < NT) {
            if (t + 2 < NT) cpwait<1>(); else cpwait<0>();
            __syncthreads();                     // buffer (t+1)&1 ready for all
        }
    }

    // ---- finalize: row sums -> normalize AO, write isum ----
    rsum0 += __shfl_xor_sync(0xFFFFFFFFu, rsum0, 1);
    rsum0 += __shfl_xor_sync(0xFFFFFFFFu, rsum0, 2);
    rsum1 += __shfl_xor_sync(0xFFFFFFFFu, rsum1, 1);
    rsum1 += __shfl_xor_sync(0xFFFFFFFFu, rsum1, 2);
    const float inv0 = 1.0f / rsum0;
    const float inv1 = 1.0f / rsum1;

    if (row0 < S_LEN) {
#pragma unroll
        for (int ni = 0; ni < 8; ni++) {
            const int d = ni * 8 + (lane & 3) * 2;
            *reinterpret_cast<__half2*>(AO + (long)row0 * E_DIM + h * 64 + d) =
                __floats2half2_rn(acc_o[ni][0] * inv0, acc_o[ni][1] * inv0);
        }
        if ((lane & 3) == 0) isum[hS + row0] = inv0;
    }
    if (row1 < S_LEN) {
#pragma unroll
        for (int ni = 0; ni < 8; ni++) {
            const int d = ni * 8 + (lane & 3) * 2;
            *reinterpret_cast<__half2*>(AO + (long)row1 * E_DIM + h * 64 + d) =
                __floats2half2_rn(acc_o[ni][2] * inv1, acc_o[ni][3] * inv1);
        }
        if ((lane & 3) == 0) isum[hS + row1] = inv1;
    }
}

// ---------------------------------------------------------------------------
// Small kernels
// ---------------------------------------------------------------------------
__global__ void splitH_kernel(const float* __restrict__ src, __half* __restrict__ dst, long n) {
    long i = ((long)blockIdx.x * blockDim.x + threadIdx.x) * 4;
    if (i >= n) return;
    float4 v = *(const float4*)(src + i);
    *(__half2*)(dst + i)     = __floats2half2_rn(v.x, v.y);
    *(__half2*)(dst + i + 2) = __floats2half2_rn(v.z, v.w);
}

__global__ void splitW4_kernel(const float* __restrict__ w0, const float* __restrict__ w1,
                               const float* __restrict__ w2, const float* __restrict__ w3,
                               __half* __restrict__ dstB) {
    const long nw = (long)E_DIM * E_DIM;
    const int z = blockIdx.z;
    const float* src = (z == 0) ? w0 : (z == 1) ? w1 : (z == 2) ? w2 : w3;
    __half* dst = dstB + (long)z * nw;
    long i = ((long)blockIdx.x * blockDim.x + threadIdx.x) * 4;
    if (i >= nw) return;
    float4 v = *(const float4*)(src + i);
    *(__half2*)(dst + i)     = __floats2half2_rn(v.x, v.y);
    *(__half2*)(dst + i + 2) = __floats2half2_rn(v.z, v.w);
}

__global__ void rope_split_kernel(const float* __restrict__ Q, const float* __restrict__ K,
                                  const float* __restrict__ cosp, const float* __restrict__ sinp) {
    const long total = (long)H_NUM * S_LEN * 32;
    long idx = (long)blockIdx.x * blockDim.x + threadIdx.x;
    if (idx >= total) return;
    const int d = (int)(idx & 31);
    const long hs = idx >> 5;
    const int s = (int)(hs % S_LEN);
    const long base = hs << 6;

    const float c1 = cosp[s * 64 + d], s1 = sinp[s * 64 + d];
    const float c2 = cosp[s * 64 + d + 32], s2 = sinp[s * 64 + d + 32];

    float q1 = Q[base + d], q2 = Q[base + d + 32];
    float k1 = K[base + d], k2 = K[base + d + 32];

    g_Qh[base + d]      = __float2half_rn((q1 * c1 - q2 * s1) * 0.125f);
    g_Qh[base + d + 32] = __float2half_rn((q2 * c2 + q1 * s2) * 0.125f);
    g_Kh[base + d]      = __float2half_rn(k1 * c1 - k2 * s1);
    g_Kh[base + d + 32] = __float2half_rn(k2 * c2 + k1 * s2);
}

__global__ void vtrans_kernel(const float* __restrict__ V) {
    __shared__ float tile[64][65];
    const int h = blockIdx.z;
    const int s0 = blockIdx.x * 64;
    const int t = threadIdx.x;
    for (int i = t; i < 4096; i += 256) {
        int s = i >> 6, d = i & 63;
        tile[s][d] = V[((long)h * S_LEN + s0 + s) * 64 + d];
    }
    __syncthreads();
    for (int i = t; i < 4096; i += 256) {
        int d = i >> 6, s = i & 63;
        float v = tile[s][d];
        __half hi = __float2half_rn(v);
        long o = ((long)h * 64 + d) * S_LEN + s0 + s;
        g_Vthi[o] = hi;
        g_Vtlo[o] = __float2half_rn(v - __half2float(hi));
    }
}

__global__ void normalize_kernel(float* __restrict__ W) {
    const long row = blockIdx.x;
    const float inv = g_isum[row];
    const __half* e = g_E + row * (long)S_LEN;
    float* w = W + row * (long)S_LEN;
    for (int i = threadIdx.x * 8; i < S_LEN; i += 256 * 8) {
        uint4 h4 = *(const uint4*)(e + i);
        const uint32_t hh[4] = {h4.x, h4.y, h4.z, h4.w};
        float o[8];
#pragma unroll
        for (int j = 0; j < 4; j++) {
            __half2 hb = *(const __half2*)&hh[j];
            o[j * 2 + 0] = __low2float(hb) * inv;
            o[j * 2 + 1] = __high2float(hb) * inv;
        }
        *(float4*)(w + i)     = make_float4(o[0], o[1], o[2], o[3]);
        *(float4*)(w + i + 4) = make_float4(o[4], o[5], o[6], o[7]);
    }
}

// ---------------------------------------------------------------------------
// Launch
// ---------------------------------------------------------------------------
extern "C" void kernel_launch(void* const* d_in, const int* in_sizes, int n_in,
                              void* d_out, int out_size) {
    const float* hidden = (const float*)d_in[0];
    const float* cosp   = (const float*)d_in[1];
    const float* sinp   = (const float*)d_in[2];
    const float* w[4]   = {(const float*)d_in[3], (const float*)d_in[4],
                           (const float*)d_in[5], (const float*)d_in[6]};

    float* out    = (float*)d_out;
    float* attn_w = out + (long)S_LEN * E_DIM;

    float* qkv; cudaGetSymbolAddress((void**)&qkv, g_qkv);
    __half *Hh, *Wh, *Qh, *Kh, *Vthi, *Vtlo, *E, *AO;
    float *isum;
    cudaGetSymbolAddress((void**)&Hh, g_Hh);
    cudaGetSymbolAddress((void**)&Wh, g_Wh);
    cudaGetSymbolAddress((void**)&Qh, g_Qh);    cudaGetSymbolAddress((void**)&Kh, g_Kh);
    cudaGetSymbolAddress((void**)&Vthi, g_Vthi); cudaGetSymbolAddress((void**)&Vtlo, g_Vtlo);
    cudaGetSymbolAddress((void**)&E, g_E);      cudaGetSymbolAddress((void**)&AO, g_AO);
    cudaGetSymbolAddress((void**)&isum, g_isum);

    static cudaStream_t s1 = nullptr;
    static cudaEvent_t evFork = nullptr, evJoin = nullptr;
    if (!s1) {
        cudaStreamCreateWithFlags(&s1, cudaStreamNonBlocking);
        cudaEventCreateWithFlags(&evFork, cudaEventDisableTiming);
        cudaEventCreateWithFlags(&evJoin, cudaEventDisableTiming);
    }

    const int SMEM_PROJ = 2 * (128 * 80 + 128 * 80);              // 40960
    const int SMEM_FA   = 128 * 176 + 2 * (128 * 176 + 2 * 64 * 272);  // 137216
    cudaFuncSetAttribute((const void*)mma_gemm<0>, cudaFuncAttributeMaxDynamicSharedMemorySize, SMEM_PROJ);
    cudaFuncSetAttribute((const void*)mma_gemm<1>, cudaFuncAttributeMaxDynamicSharedMemorySize, SMEM_PROJ);
    cudaFuncSetAttribute((const void*)fused_attn,  cudaFuncAttributeMaxDynamicSharedMemorySize, SMEM_FA);

    // 1) fp16 conversions
    {
        long n = (long)S_LEN * E_DIM;
        splitH_kernel<<<(int)((n / 4 + 255) / 256), 256>>>(hidden, Hh, n);
        long nw = (long)E_DIM * E_DIM;
        dim3 gw((unsigned)((nw / 4 + 255) / 256), 1, 4);
        splitW4_kernel<<<gw, 256>>>(w[0], w[1], w[2], w[3], Wh);
    }

    // 2) QKV projections (1-pass fp16), batched over z={q,k,v}
    {
        dim3 g(E_DIM / 128, (S_LEN + 127) / 128, 3);
        mma_gemm<1><<<g, 256, SMEM_PROJ>>>(Hh, E_DIM,
                                           Wh, E_DIM, (long)E_DIM * E_DIM,
                                           qkv, 0, 0, 32, S_LEN);
    }

    // 3) RoPE -> fp16 Q (scaled), K; V transpose + fp16 split
    {
        long total = (long)H_NUM * S_LEN * 32;
        const long HSD = (long)H_NUM * S_LEN * D_DIM;
        rope_split_kernel<<<(int)((total + 255) / 256), 256>>>(qkv, qkv + HSD, cosp, sinp);
        dim3 gv(S_LEN / 64, 1, H_NUM);
        vtrans_kernel<<<gv, 256>>>(qkv + 2 * HSD);
    }

    // 4) fused attention: E (fp16) + isum + normalized AO in one kernel
    {
        dim3 g((S_LEN + 127) / 128, H_NUM);
        fused_attn<<<g, 256, SMEM_FA>>>(Qh, Kh, Vthi, Vtlo, E, AO, isum);
    }

    // 5) FORK: normalize (attn_weights fp32) on side stream, overlapped with out-proj
    cudaEventRecord(evFork, 0);
    cudaStreamWaitEvent(s1, evFork, 0);
    normalize_kernel<<<H_NUM * S_LEN, 256, 0, s1>>>(attn_w);
    cudaEventRecord(evJoin, s1);

    // 6) out = AO Wo^T (1-pass fp16)  [main stream]
    {
        dim3 g(E_DIM / 128, (S_LEN + 127) / 128, 1);
        long nw = (long)E_DIM * E_DIM;
        mma_gemm<0><<<g, 256, SMEM_PROJ>>>(AO, E_DIM,
                                           Wh + 3 * nw, E_DIM, 0,
                                           out, E_DIM, 0, 32, S_LEN);
    }

    // 7) JOIN
    cudaStreamWaitEvent(0, evJoin, 0);
}

// round 12
// speedup vs baseline: 2.0323x; 1.0901x over previous
#include <cuda_runtime.h>
#include <cuda_fp16.h>
#include <math.h>
#include <stdint.h>

#define S_LEN 3136
#define E_DIM 1024
#define H_NUM 16
#define D_DIM 64

// ---------------------------------------------------------------------------
// Device scratch (allocation is forbidden)
// ---------------------------------------------------------------------------
__device__ float g_qkv[3][H_NUM * S_LEN * D_DIM];   // fp32 head-major q,k,v

__device__ __align__(16) __half g_Hh[S_LEN * E_DIM];            // hidden fp16
__device__ __align__(16) __half g_Wh[4][E_DIM * E_DIM];         // weights fp16
__device__ __align__(16) __half g_Qh[H_NUM * S_LEN * D_DIM];    // q fp16 (scaled 1/8)
__device__ __align__(16) __half g_Kh[H_NUM * S_LEN * D_DIM];    // k fp16
__device__ __align__(16) __half g_Vt[H_NUM * D_DIM * S_LEN];    // [h][d][s] fp16
__device__ __align__(16) __half g_E[(long)H_NUM * S_LEN * S_LEN]; // unnormalized exp
__device__ __align__(16) __half g_AO[S_LEN * E_DIM];            // normalized attn out
__device__ float g_isum[H_NUM * S_LEN];                         // 1 / rowsum

// ---------------------------------------------------------------------------
// PTX helpers
// ---------------------------------------------------------------------------
__device__ __forceinline__ uint32_t smem_u32(const void* p) {
    uint32_t a;
    asm("{ .reg .u64 t; cvta.to.shared.u64 t, %1; cvt.u32.u64 %0, t; }" : "=r"(a) : "l"(p));
    return a;
}
__device__ __forceinline__ void cp16(uint32_t dst, const void* src, int srcsize) {
    asm volatile("cp.async.cg.shared.global [%0], [%1], 16, %2;"
                 :: "r"(dst), "l"(src), "r"(srcsize));
}
__device__ __forceinline__ void cpcommit() { asm volatile("cp.async.commit_group;"); }
template <int N> __device__ __forceinline__ void cpwait() {
    asm volatile("cp.async.wait_group %0;" :: "n"(N));
}
__device__ __forceinline__ void ldm4(uint32_t* r, uint32_t a) {
    asm volatile("ldmatrix.sync.aligned.m8n8.x4.shared.b16 {%0,%1,%2,%3}, [%4];"
                 : "=r"(r[0]), "=r"(r[1]), "=r"(r[2]), "=r"(r[3]) : "r"(a));
}
__device__ __forceinline__ void ldm2(uint32_t* r, uint32_t a) {
    asm volatile("ldmatrix.sync.aligned.m8n8.x2.shared.b16 {%0,%1}, [%2];"
                 : "=r"(r[0]), "=r"(r[1]) : "r"(a));
}
__device__ __forceinline__ void mma16816(float* d, const uint32_t* a, const uint32_t* b) {
    asm volatile("mma.sync.aligned.m16n8k16.row.col.f32.f16.f16.f32 "
                 "{%0,%1,%2,%3}, {%4,%5,%6,%7}, {%8,%9}, {%0,%1,%2,%3};"
                 : "+f"(d[0]), "+f"(d[1]), "+f"(d[2]), "+f"(d[3])
                 : "r"(a[0]), "r"(a[1]), "r"(a[2]), "r"(a[3]), "r"(b[0]), "r"(b[1]));
}

// ---------------------------------------------------------------------------
// fp16 single/single TN GEMM (proven core) for QKV-proj and out-proj.
// EPI 0: fp32 C[z*cBatch + m*ldc + n]
// EPI 1: fp32 head-major qkv: C[(z*H + (n>>6))*S*64 + m*64 + (n&63)]
// ---------------------------------------------------------------------------
template <int EPI>
__global__ void __launch_bounds__(256, 1) mma_gemm(
    const __half* __restrict__ A, long aRow,
    const __half* __restrict__ B, long bRow, long bBatch,
    float* __restrict__ C, long ldc, long cBatch,
    int kChunks, int M_valid) {

    constexpr int AST = 80;
    constexpr int A_BYTES = 128 * AST;
    constexpr int B_BYTES = 128 * AST;
    constexpr int STAGE = A_BYTES + B_BYTES;

    extern __shared__ char smem[];
    const uint32_t sb = smem_u32(smem);

    const int tid = threadIdx.x;
    const int wid = tid >> 5, lane = tid & 31;
    const int warpM = (wid / 4) * 64;
    const int warpN = (wid % 4) * 32;

    const int mBase = blockIdx.y * 128;
    const int nBase = blockIdx.x * 128;
    const int z = blockIdx.z;
    B += bBatch * z;

    float acc[4][4][4];
#pragma unroll
    for (int i = 0; i < 4; i++)
#pragma unroll
        for (int j = 0; j < 4; j++)
#pragma unroll
            for (int q = 0; q < 4; q++) acc[i][j][q] = 0.0f;

    auto issue_loads = [&](int c) {
        const long k0 = (long)c * 32;
        const uint32_t st = sb + (c & 1) * STAGE;
        for (int i = tid; i < 512; i += 256) {
            const int r = i >> 2, u = i & 3;
            const int row = mBase + r;
            const int ok = (row < M_valid) ? 16 : 0;
            const long srow = (row < M_valid) ? row : (M_valid - 1);
            cp16(st + r * AST + u * 16, A + srow * aRow + k0 + u * 8, ok);
        }
        for (int i = tid; i < 512; i += 256) {
            const int r = i >> 2, u = i & 3;
            cp16(st + A_BYTES + r * AST + u * 16, B + (long)(nBase + r) * bRow + k0 + u * 8, 16);
        }
        cpcommit();
    };

    issue_loads(0);

    for (int c = 0; c < kChunks; c++) {
        if (c + 1 < kChunks) { issue_loads(c + 1); cpwait<1>(); }
        else                 { cpwait<0>(); }
        __syncthreads();

        const uint32_t st = sb + (c & 1) * STAGE;
        const uint32_t aB = st, bB = st + A_BYTES;

#pragma unroll
        for (int s = 0; s < 2; s++) {
            uint32_t af[4][4], bf[4][2];
            const int arow = warpM + (lane & 15);
            const uint32_t acol = s * 32 + (lane >> 4) * 16;
#pragma unroll
            for (int mi = 0; mi < 4; mi++)
                ldm4(af[mi], aB + (uint32_t)((arow + mi * 16) * AST) + acol);
            const int l16 = lane & 15;
            const int brow = warpN + (l16 & 7);
            const uint32_t bcol = s * 32 + (l16 >> 3) * 16;
#pragma unroll
            for (int ni = 0; ni < 4; ni++)
                ldm2(bf[ni], bB + (uint32_t)((brow + ni * 8) * AST) + bcol);
#pragma unroll
            for (int mi = 0; mi < 4; mi++)
#pragma unroll
                for (int ni = 0; ni < 4; ni++)
                    mma16816(acc[mi][ni], af[mi], bf[ni]);
        }
        __syncthreads();
    }

#pragma unroll
    for (int mi = 0; mi < 4; mi++) {
#pragma unroll
        for (int ni = 0; ni < 4; ni++) {
            const int rl0 = warpM + mi * 16 + (lane >> 2);
            const int col0 = nBase + warpN + ni * 8 + (lane & 3) * 2;
#pragma unroll
            for (int h = 0; h < 2; h++) {
                const int row = mBase + rl0 + h * 8;
                if (row >= M_valid) continue;
                const float v0 = acc[mi][ni][h * 2 + 0];
                const float v1 = acc[mi][ni][h * 2 + 1];
                if (EPI == 0) {
                    C[(long)z * cBatch + (long)row * ldc + col0] = v0;
                    C[(long)z * cBatch + (long)row * ldc + col0 + 1] = v1;
                } else {
                    const long o0 = ((long)z * H_NUM + (col0 >> 6)) * S_LEN * 64 + (long)row * 64 + (col0 & 63);
                    C[o0] = v0;
                    C[o0 + 1] = v1;
                }
            }
        }
    }
}

// ---------------------------------------------------------------------------
// Fused attention: per (m-tile 128, head) CTA, loop 25 K/V tiles:
//   S = Q Kt (MMA) -> exp -> write fp16 E + rowsum in regs -> pack P frags
//   -> AO_acc += P * V (single fp16 V). Finalize: AO *= 1/rowsum, write isum.
// ---------------------------------------------------------------------------
__global__ void __launch_bounds__(256, 1) fused_attn(
    const __half* __restrict__ Qh, const __half* __restrict__ Kh,
    const __half* __restrict__ V,
    __half* __restrict__ E, __half* __restrict__ AO, float* __restrict__ isum) {

    constexpr int QK_ST = 176;                    // 64 halves + pad (conflict-free)
    constexpr int V_ST  = 272;                    // 128 halves + pad
    constexpr int Q_BYTES = 128 * QK_ST;          // 22528
    constexpr int K_BYTES = 128 * QK_ST;          // 22528
    constexpr int V_BYTES = 64 * V_ST;            // 17408
    constexpr int STAGE = K_BYTES + V_BYTES;      // 39936
    constexpr int NT = 25;                        // ceil(S/128)

    extern __shared__ char smem[];
    const uint32_t sb = smem_u32(smem);
    const uint32_t qb = sb;
    const uint32_t stb = sb + Q_BYTES;

    const int tid = threadIdx.x;
    const int w = tid >> 5, lane = tid & 31;
    const int h = blockIdx.y;
    const int mBase = blockIdx.x * 128;
    const long hS = (long)h * S_LEN;

    // ---- issue Q tile + KV stage 0 (one group), then KV stage 1 ----
    for (int i = tid; i < 1024; i += 256) {
        const int r = i >> 3, u = i & 7;
        const int row = mBase + r;
        const int ok = (row < S_LEN) ? 16 : 0;
        const long srow = (row < S_LEN) ? row : (S_LEN - 1);
        cp16(qb + r * QK_ST + u * 16, Qh + (hS + srow) * 64 + u * 8, ok);
    }
    auto issue_kv = [&](int t) {
        const int kBase = t * 128;
        const uint32_t st = stb + (t & 1) * STAGE;
        for (int i = tid; i < 1024; i += 256) {
            const int r = i >> 3, u = i & 7;
            const int row = kBase + r;
            const int ok = (row < S_LEN) ? 16 : 0;
            const long srow = (row < S_LEN) ? row : (S_LEN - 1);
            cp16(st + r * QK_ST + u * 16, Kh + (hS + srow) * 64 + u * 8, ok);
        }
        for (int i = tid; i < 1024; i += 256) {
            const int r = i >> 4, u = i & 15;     // r: d-row 0..63, u: 8-half col group
            const int col = kBase + u * 8;
            const int ok = (col < S_LEN) ? 16 : 0;
            const long scol = (col < S_LEN) ? col : (S_LEN - 8);
            const long off = ((long)h * 64 + r) * S_LEN + scol;
            cp16(st + K_BYTES + r * V_ST + u * 16, V + off, ok);
        }
        cpcommit();
    };
    issue_kv(0);               // commits Q + stage0 together
    issue_kv(1);
    cpwait<1>();               // Q + stage0 ready
    __syncthreads();

    // ---- Q fragments (held in registers all kernel) ----
    uint32_t qf[4][4];
    {
        const int arow = w * 16 + (lane & 15);
        const uint32_t acol = (uint32_t)((lane >> 4) * 16);
#pragma unroll
        for (int ks = 0; ks < 4; ks++)
            ldm4(qf[ks], qb + (uint32_t)(arow * QK_ST) + ks * 32 + acol);
    }

    float acc_o[8][4];
#pragma unroll
    for (int i = 0; i < 8; i++)
#pragma unroll
        for (int q = 0; q < 4; q++) acc_o[i][q] = 0.0f;
    float rsum0 = 0.0f, rsum1 = 0.0f;

    const int row0 = mBase + w * 16 + (lane >> 2);
    const int row1 = row0 + 8;
    const int l16 = lane & 15;
    const int brow_off = l16 & 7;
    const uint32_t bcol_off = (uint32_t)((l16 >> 3) * 16);

    for (int t = 0; t < NT; t++) {
        const uint32_t st = stb + (t & 1) * STAGE;
        const int kBase = t * 128;

        // ---- score MMAs: acc[ni] (16 rows x 128 cols per warp) ----
        float acc[16][4];
#pragma unroll
        for (int i = 0; i < 16; i++)
#pragma unroll
            for (int q = 0; q < 4; q++) acc[i][q] = 0.0f;
#pragma unroll
        for (int ks = 0; ks < 4; ks++) {
#pragma unroll
            for (int ni = 0; ni < 16; ni++) {
                uint32_t b[2];
                ldm2(b, st + (uint32_t)((ni * 8 + brow_off) * QK_ST) + ks * 32 + bcol_off);
                mma16816(acc[ni], qf[ks], b);
            }
        }

        // ---- exp + E write + rowsum + pack P fragments ----
        uint32_t eh[32];
#pragma unroll
        for (int ni = 0; ni < 16; ni++) {
            const int col0 = kBase + ni * 8 + (lane & 3) * 2;
            float e00 = 0.f, e01 = 0.f, e10 = 0.f, e11 = 0.f;
            if (col0 < S_LEN) {
                e00 = __expf(acc[ni][0]); e01 = __expf(acc[ni][1]);
                e10 = __expf(acc[ni][2]); e11 = __expf(acc[ni][3]);
            }
            const __half2 hv0 = __floats2half2_rn(e00, e01);
            const __half2 hv1 = __floats2half2_rn(e10, e11);
            eh[ni * 2]     = *(const uint32_t*)&hv0;
            eh[ni * 2 + 1] = *(const uint32_t*)&hv1;
            if (col0 < S_LEN) {
                if (row0 < S_LEN) *reinterpret_cast<__half2*>(E + (hS + row0) * S_LEN + col0) = hv0;
                if (row1 < S_LEN) *reinterpret_cast<__half2*>(E + (hS + row1) * S_LEN + col0) = hv1;
                rsum0 += __low2float(hv0) + __high2float(hv0);
                rsum1 += __low2float(hv1) + __high2float(hv1);
            }
        }

        // ---- PV MMAs: acc_o += P * V ----
#pragma unroll
        for (int ks = 0; ks < 8; ks++) {
#pragma unroll
            for (int ni = 0; ni < 8; ni++) {
                uint32_t b[2];
                ldm2(b, st + K_BYTES + (uint32_t)((ni * 8 + brow_off) * V_ST) + ks * 32 + bcol_off);
                mma16816(acc_o[ni], &eh[ks * 4], b);
            }
        }

        __syncthreads();                         // all warps done reading buffer t&1
        if (t + 2 < NT) issue_kv(t + 2);         // refill buffer t&1
        if (t + 1 < NT) {
            if (t + 2 < NT) cpwait<1>(); else cpwait<0>();
            __syncthreads();                     // buffer (t+1)&1 ready for all
        }
    }

    // ---- finalize: row sums -> normalize AO, write isum ----
    rsum0 += __shfl_xor_sync(0xFFFFFFFFu, rsum0, 1);
    rsum0 += __shfl_xor_sync(0xFFFFFFFFu, rsum0, 2);
    rsum1 += __shfl_xor_sync(0xFFFFFFFFu, rsum1, 1);
    rsum1 += __shfl_xor_sync(0xFFFFFFFFu, rsum1, 2);
    const float inv0 = 1.0f / rsum0;
    const float inv1 = 1.0f / rsum1;

    if (row0 < S_LEN) {
#pragma unroll
        for (int ni = 0; ni < 8; ni++) {
            const int d = ni * 8 + (lane & 3) * 2;
            *reinterpret_cast<__half2*>(AO + (long)row0 * E_DIM + h * 64 + d) =
                __floats2half2_rn(acc_o[ni][0] * inv0, acc_o[ni][1] * inv0);
        }
        if ((lane & 3) == 0) isum[hS + row0] = inv0;
    }
    if (row1 < S_LEN) {
#pragma unroll
        for (int ni = 0; ni < 8; ni++) {
            const int d = ni * 8 + (lane & 3) * 2;
            *reinterpret_cast<__half2*>(AO + (long)row1 * E_DIM + h * 64 + d) =
                __floats2half2_rn(acc_o[ni][2] * inv1, acc_o[ni][3] * inv1);
        }
        if ((lane & 3) == 0) isum[hS + row1] = inv1;
    }
}

// ---------------------------------------------------------------------------
// Small kernels
// ---------------------------------------------------------------------------
__global__ void splitH_kernel(const float* __restrict__ src, __half* __restrict__ dst, long n) {
    long i = ((long)blockIdx.x * blockDim.x + threadIdx.x) * 4;
    if (i >= n) return;
    float4 v = *(const float4*)(src + i);
    *(__half2*)(dst + i)     = __floats2half2_rn(v.x, v.y);
    *(__half2*)(dst + i + 2) = __floats2half2_rn(v.z, v.w);
}

__global__ void splitW4_kernel(const float* __restrict__ w0, const float* __restrict__ w1,
                               const float* __restrict__ w2, const float* __restrict__ w3,
                               __half* __restrict__ dstB) {
    const long nw = (long)E_DIM * E_DIM;
    const int z = blockIdx.z;
    const float* src = (z == 0) ? w0 : (z == 1) ? w1 : (z == 2) ? w2 : w3;
    __half* dst = dstB + (long)z * nw;
    long i = ((long)blockIdx.x * blockDim.x + threadIdx.x) * 4;
    if (i >= nw) return;
    float4 v = *(const float4*)(src + i);
    *(__half2*)(dst + i)     = __floats2half2_rn(v.x, v.y);
    *(__half2*)(dst + i + 2) = __floats2half2_rn(v.z, v.w);
}

__global__ void rope_split_kernel(const float* __restrict__ Q, const float* __restrict__ K,
                                  const float* __restrict__ cosp, const float* __restrict__ sinp) {
    const long total = (long)H_NUM * S_LEN * 32;
    long idx = (long)blockIdx.x * blockDim.x + threadIdx.x;
    if (idx >= total) return;
    const int d = (int)(idx & 31);
    const long hs = idx >> 5;
    const int s = (int)(hs % S_LEN);
    const long base = hs << 6;

    const float c1 = cosp[s * 64 + d], s1 = sinp[s * 64 + d];
    const float c2 = cosp[s * 64 + d + 32], s2 = sinp[s * 64 + d + 32];

    float q1 = Q[base + d], q2 = Q[base + d + 32];
    float k1 = K[base + d], k2 = K[base + d + 32];

    g_Qh[base + d]      = __float2half_rn((q1 * c1 - q2 * s1) * 0.125f);
    g_Qh[base + d + 32] = __float2half_rn((q2 * c2 + q1 * s2) * 0.125f);
    g_Kh[base + d]      = __float2half_rn(k1 * c1 - k2 * s1);
    g_Kh[base + d + 32] = __float2half_rn(k2 * c2 + k1 * s2);
}

// V transpose: fp32 [h][s][64] -> fp16 [h][d][s]
__global__ void vtrans_kernel(const float* __restrict__ V) {
    __shared__ float tile[64][65];
    const int h = blockIdx.z;
    const int s0 = blockIdx.x * 64;
    const int t = threadIdx.x;
    for (int i = t; i < 4096; i += 256) {
        int s = i >> 6, d = i & 63;
        tile[s][d] = V[((long)h * S_LEN + s0 + s) * 64 + d];
    }
    __syncthreads();
    for (int i = t; i < 4096; i += 256) {
        int d = i >> 6, s = i & 63;
        g_Vt[((long)h * 64 + d) * S_LEN + s0 + s] = __float2half_rn(tile[s][d]);
    }
}

__global__ void normalize_kernel(float* __restrict__ W) {
    const long row = blockIdx.x;
    const float inv = g_isum[row];
    const __half* e = g_E + row * (long)S_LEN;
    float* w = W + row * (long)S_LEN;
    for (int i = threadIdx.x * 8; i < S_LEN; i += 256 * 8) {
        uint4 h4 = *(const uint4*)(e + i);
        const uint32_t hh[4] = {h4.x, h4.y, h4.z, h4.w};
        float o[8];
#pragma unroll
        for (int j = 0; j < 4; j++) {
            __half2 hb = *(const __half2*)&hh[j];
            o[j * 2 + 0] = __low2float(hb) * inv;
            o[j * 2 + 1] = __high2float(hb) * inv;
        }
        *(float4*)(w + i)     = make_float4(o[0], o[1], o[2], o[3]);
        *(float4*)(w + i + 4) = make_float4(o[4], o[5], o[6], o[7]);
    }
}

// ---------------------------------------------------------------------------
// Launch
// ---------------------------------------------------------------------------
extern "C" void kernel_launch(void* const* d_in, const int* in_sizes, int n_in,
                              void* d_out, int out_size) {
    const float* hidden = (const float*)d_in[0];
    const float* cosp   = (const float*)d_in[1];
    const float* sinp   = (const float*)d_in[2];
    const float* w[4]   = {(const float*)d_in[3], (const float*)d_in[4],
                           (const float*)d_in[5], (const float*)d_in[6]};

    float* out    = (float*)d_out;
    float* attn_w = out + (long)S_LEN * E_DIM;

    float* qkv; cudaGetSymbolAddress((void**)&qkv, g_qkv);
    __half *Hh, *Wh, *Qh, *Kh, *Vt, *E, *AO;
    float *isum;
    cudaGetSymbolAddress((void**)&Hh, g_Hh);
    cudaGetSymbolAddress((void**)&Wh, g_Wh);
    cudaGetSymbolAddress((void**)&Qh, g_Qh);    cudaGetSymbolAddress((void**)&Kh, g_Kh);
    cudaGetSymbolAddress((void**)&Vt, g_Vt);
    cudaGetSymbolAddress((void**)&E, g_E);      cudaGetSymbolAddress((void**)&AO, g_AO);
    cudaGetSymbolAddress((void**)&isum, g_isum);

    static cudaStream_t s1 = nullptr;
    static cudaEvent_t evFork = nullptr, evJoin = nullptr;
    if (!s1) {
        cudaStreamCreateWithFlags(&s1, cudaStreamNonBlocking);
        cudaEventCreateWithFlags(&evFork, cudaEventDisableTiming);
        cudaEventCreateWithFlags(&evJoin, cudaEventDisableTiming);
    }

    const int SMEM_PROJ = 2 * (128 * 80 + 128 * 80);                 // 40960
    const int SMEM_FA   = 128 * 176 + 2 * (128 * 176 + 64 * 272);    // 102400
    cudaFuncSetAttribute((const void*)mma_gemm<0>, cudaFuncAttributeMaxDynamicSharedMemorySize, SMEM_PROJ);
    cudaFuncSetAttribute((const void*)mma_gemm<1>, cudaFuncAttributeMaxDynamicSharedMemorySize, SMEM_PROJ);
    cudaFuncSetAttribute((const void*)fused_attn,  cudaFuncAttributeMaxDynamicSharedMemorySize, SMEM_FA);

    // 1) fp16 conversions
    {
        long n = (long)S_LEN * E_DIM;
        splitH_kernel<<<(int)((n / 4 + 255) / 256), 256>>>(hidden, Hh, n);
        long nw = (long)E_DIM * E_DIM;
        dim3 gw((unsigned)((nw / 4 + 255) / 256), 1, 4);
        splitW4_kernel<<<gw, 256>>>(w[0], w[1], w[2], w[3], Wh);
    }

    // 2) QKV projections (1-pass fp16), batched over z={q,k,v}
    {
        dim3 g(E_DIM / 128, (S_LEN + 127) / 128, 3);
        mma_gemm<1><<<g, 256, SMEM_PROJ>>>(Hh, E_DIM,
                                           Wh, E_DIM, (long)E_DIM * E_DIM,
                                           qkv, 0, 0, 32, S_LEN);
    }

    // 3) RoPE -> fp16 Q (scaled), K; V transpose (fp16 single)
    {
        long total = (long)H_NUM * S_LEN * 32;
        const long HSD = (long)H_NUM * S_LEN * D_DIM;
        rope_split_kernel<<<(int)((total + 255) / 256), 256>>>(qkv, qkv + HSD, cosp, sinp);
        dim3 gv(S_LEN / 64, 1, H_NUM);
        vtrans_kernel<<<gv, 256>>>(qkv + 2 * HSD);
    }

    // 4) fused attention: E (fp16) + isum + normalized AO in one kernel
    {
        dim3 g((S_LEN + 127) / 128, H_NUM);
        fused_attn<<<g, 256, SMEM_FA>>>(Qh, Kh, Vt, E, AO, isum);
    }

    // 5) FORK: normalize (attn_weights fp32) on side stream, overlapped with out-proj
    cudaEventRecord(evFork, 0);
    cudaStreamWaitEvent(s1, evFork, 0);
    normalize_kernel<<<H_NUM * S_LEN, 256, 0, s1>>>(attn_w);
    cudaEventRecord(evJoin, s1);

    // 6) out = AO Wo^T (1-pass fp16)  [main stream]
    {
        dim3 g(E_DIM / 128, (S_LEN + 127) / 128, 1);
        long nw = (long)E_DIM * E_DIM;
        mma_gemm<0><<<g, 256, SMEM_PROJ>>>(AO, E_DIM,
                                           Wh + 3 * nw, E_DIM, 0,
                                           out, E_DIM, 0, 32, S_LEN);
    }

    // 7) JOIN
    cudaStreamWaitEvent(0, evJoin, 0);
}

// round 13
// speedup vs baseline: 2.0508x; 1.0091x over previous
#include <cuda_runtime.h>
#include <cuda_fp16.h>
#include <math.h>
#include <stdint.h>

#define S_LEN 3136
#define E_DIM 1024
#define H_NUM 16
#define D_DIM 64

// ---------------------------------------------------------------------------
// Device scratch (allocation is forbidden)
// ---------------------------------------------------------------------------
__device__ float g_qkv[3][H_NUM * S_LEN * D_DIM];   // fp32 head-major q,k,v

__device__ __align__(16) __half g_Hh[S_LEN * E_DIM];            // hidden fp16
__device__ __align__(16) __half g_Wh[4][E_DIM * E_DIM];         // weights fp16
__device__ __align__(16) __half g_Qh[H_NUM * S_LEN * D_DIM];    // q fp16 (scaled 1/8)
__device__ __align__(16) __half g_Kh[H_NUM * S_LEN * D_DIM];    // k fp16
__device__ __align__(16) __half g_Vt[H_NUM * D_DIM * S_LEN];    // [h][d][s] fp16
__device__ __align__(16) __half g_E[(long)H_NUM * S_LEN * S_LEN]; // unnormalized exp
__device__ __align__(16) __half g_AO[S_LEN * E_DIM];            // normalized attn out
__device__ float g_isum[H_NUM * S_LEN];                         // 1 / rowsum

// ---------------------------------------------------------------------------
// PTX helpers
// ---------------------------------------------------------------------------
__device__ __forceinline__ uint32_t smem_u32(const void* p) {
    uint32_t a;
    asm("{ .reg .u64 t; cvta.to.shared.u64 t, %1; cvt.u32.u64 %0, t; }" : "=r"(a) : "l"(p));
    return a;
}
__device__ __forceinline__ void cp16(uint32_t dst, const void* src, int srcsize) {
    asm volatile("cp.async.cg.shared.global [%0], [%1], 16, %2;"
                 :: "r"(dst), "l"(src), "r"(srcsize));
}
__device__ __forceinline__ void cpcommit() { asm volatile("cp.async.commit_group;"); }
template <int N> __device__ __forceinline__ void cpwait() {
    asm volatile("cp.async.wait_group %0;" :: "n"(N));
}
__device__ __forceinline__ void ldm4(uint32_t* r, uint32_t a) {
    asm volatile("ldmatrix.sync.aligned.m8n8.x4.shared.b16 {%0,%1,%2,%3}, [%4];"
                 : "=r"(r[0]), "=r"(r[1]), "=r"(r[2]), "=r"(r[3]) : "r"(a));
}
__device__ __forceinline__ void mma16816(float* d, const uint32_t* a, const uint32_t* b) {
    asm volatile("mma.sync.aligned.m16n8k16.row.col.f32.f16.f16.f32 "
                 "{%0,%1,%2,%3}, {%4,%5,%6,%7}, {%8,%9}, {%0,%1,%2,%3};"
                 : "+f"(d[0]), "+f"(d[1]), "+f"(d[2]), "+f"(d[3])
                 : "r"(a[0]), "r"(a[1]), "r"(a[2]), "r"(a[3]), "r"(b[0]), "r"(b[1]));
}

// ---------------------------------------------------------------------------
// fp16 single/single TN GEMM for QKV-proj and out-proj.
// B fragments loaded pairwise with ldmatrix.x4 (rows n..n+15).
// EPI 0: fp32 C[z*cBatch + m*ldc + n]
// EPI 1: fp32 head-major qkv: C[(z*H + (n>>6))*S*64 + m*64 + (n&63)]
// ---------------------------------------------------------------------------
template <int EPI>
__global__ void __launch_bounds__(256, 1) mma_gemm(
    const __half* __restrict__ A, long aRow,
    const __half* __restrict__ B, long bRow, long bBatch,
    float* __restrict__ C, long ldc, long cBatch,
    int kChunks, int M_valid) {

    constexpr int AST = 80;
    constexpr int A_BYTES = 128 * AST;
    constexpr int B_BYTES = 128 * AST;
    constexpr int STAGE = A_BYTES + B_BYTES;

    extern __shared__ char smem[];
    const uint32_t sb = smem_u32(smem);

    const int tid = threadIdx.x;
    const int wid = tid >> 5, lane = tid & 31;
    const int warpM = (wid / 4) * 64;
    const int warpN = (wid % 4) * 32;

    const int mBase = blockIdx.y * 128;
    const int nBase = blockIdx.x * 128;
    const int z = blockIdx.z;
    B += bBatch * z;

    // x4 B addressing: groups of 8 lanes -> (row block, k half)
    const int xrow = (lane & 7) + ((lane >> 4) << 3);   // +8 for lanes 16-31
    const int xcol = ((lane >> 3) & 1) * 16;            // +16B for k8-15 half

    float acc[4][4][4];
#pragma unroll
    for (int i = 0; i < 4; i++)
#pragma unroll
        for (int j = 0; j < 4; j++)
#pragma unroll
            for (int q = 0; q < 4; q++) acc[i][j][q] = 0.0f;

    auto issue_loads = [&](int c) {
        const long k0 = (long)c * 32;
        const uint32_t st = sb + (c & 1) * STAGE;
        for (int i = tid; i < 512; i += 256) {
            const int r = i >> 2, u = i & 3;
            const int row = mBase + r;
            const int ok = (row < M_valid) ? 16 : 0;
            const long srow = (row < M_valid) ? row : (M_valid - 1);
            cp16(st + r * AST + u * 16, A + srow * aRow + k0 + u * 8, ok);
        }
        for (int i = tid; i < 512; i += 256) {
            const int r = i >> 2, u = i & 3;
            cp16(st + A_BYTES + r * AST + u * 16, B + (long)(nBase + r) * bRow + k0 + u * 8, 16);
        }
        cpcommit();
    };

    issue_loads(0);

    for (int c = 0; c < kChunks; c++) {
        if (c + 1 < kChunks) { issue_loads(c + 1); cpwait<1>(); }
        else                 { cpwait<0>(); }
        __syncthreads();

        const uint32_t st = sb + (c & 1) * STAGE;
        const uint32_t aB = st, bB = st + A_BYTES;

#pragma unroll
        for (int s = 0; s < 2; s++) {
            uint32_t af[4][4], bf[2][4];
            const int arow = warpM + (lane & 15);
            const uint32_t acol = s * 32 + (lane >> 4) * 16;
#pragma unroll
            for (int mi = 0; mi < 4; mi++)
                ldm4(af[mi], aB + (uint32_t)((arow + mi * 16) * AST) + acol);
#pragma unroll
            for (int n2 = 0; n2 < 2; n2++)
                ldm4(bf[n2], bB + (uint32_t)((warpN + n2 * 16 + xrow) * AST) + s * 32 + xcol);
#pragma unroll
            for (int mi = 0; mi < 4; mi++)
#pragma unroll
                for (int n2 = 0; n2 < 2; n2++) {
                    mma16816(acc[mi][n2 * 2 + 0], af[mi], &bf[n2][0]);
                    mma16816(acc[mi][n2 * 2 + 1], af[mi], &bf[n2][2]);
                }
        }
        __syncthreads();
    }

#pragma unroll
    for (int mi = 0; mi < 4; mi++) {
#pragma unroll
        for (int ni = 0; ni < 4; ni++) {
            const int rl0 = warpM + mi * 16 + (lane >> 2);
            const int col0 = nBase + warpN + ni * 8 + (lane & 3) * 2;
#pragma unroll
            for (int h = 0; h < 2; h++) {
                const int row = mBase + rl0 + h * 8;
                if (row >= M_valid) continue;
                const float v0 = acc[mi][ni][h * 2 + 0];
                const float v1 = acc[mi][ni][h * 2 + 1];
                if (EPI == 0) {
                    C[(long)z * cBatch + (long)row * ldc + col0] = v0;
                    C[(long)z * cBatch + (long)row * ldc + col0 + 1] = v1;
                } else {
                    const long o0 = ((long)z * H_NUM + (col0 >> 6)) * S_LEN * 64 + (long)row * 64 + (col0 & 63);
                    C[o0] = v0;
                    C[o0 + 1] = v1;
                }
            }
        }
    }
}

// ---------------------------------------------------------------------------
// Fused attention: per (m-tile 128, head) CTA, loop 25 K/V tiles:
//   S = Q Kt -> exp -> write fp16 E + rowsum in regs -> P frags -> AO += P*V.
//   K and V fragments loaded pairwise with ldmatrix.x4.
// ---------------------------------------------------------------------------
__global__ void __launch_bounds__(256, 1) fused_attn(
    const __half* __restrict__ Qh, const __half* __restrict__ Kh,
    const __half* __restrict__ V,
    __half* __restrict__ E, __half* __restrict__ AO, float* __restrict__ isum) {

    constexpr int QK_ST = 176;                    // 64 halves + pad
    constexpr int V_ST  = 272;                    // 128 halves + pad
    constexpr int Q_BYTES = 128 * QK_ST;
    constexpr int K_BYTES = 128 * QK_ST;
    constexpr int V_BYTES = 64 * V_ST;
    constexpr int STAGE = K_BYTES + V_BYTES;
    constexpr int NT = 25;

    extern __shared__ char smem[];
    const uint32_t sb = smem_u32(smem);
    const uint32_t qb = sb;
    const uint32_t stb = sb + Q_BYTES;

    const int tid = threadIdx.x;
    const int w = tid >> 5, lane = tid & 31;
    const int h = blockIdx.y;
    const int mBase = blockIdx.x * 128;
    const long hS = (long)h * S_LEN;

    for (int i = tid; i < 1024; i += 256) {
        const int r = i >> 3, u = i & 7;
        const int row = mBase + r;
        const int ok = (row < S_LEN) ? 16 : 0;
        const long srow = (row < S_LEN) ? row : (S_LEN - 1);
        cp16(qb + r * QK_ST + u * 16, Qh + (hS + srow) * 64 + u * 8, ok);
    }
    auto issue_kv = [&](int t) {
        const int kBase = t * 128;
        const uint32_t st = stb + (t & 1) * STAGE;
        for (int i = tid; i < 1024; i += 256) {
            const int r = i >> 3, u = i & 7;
            const int row = kBase + r;
            const int ok = (row < S_LEN) ? 16 : 0;
            const long srow = (row < S_LEN) ? row : (S_LEN - 1);
            cp16(st + r * QK_ST + u * 16, Kh + (hS + srow) * 64 + u * 8, ok);
        }
        for (int i = tid; i < 1024; i += 256) {
            const int r = i >> 4, u = i & 15;
            const int col = kBase + u * 8;
            const int ok = (col < S_LEN) ? 16 : 0;
            const long scol = (col < S_LEN) ? col : (S_LEN - 8);
            const long off = ((long)h * 64 + r) * S_LEN + scol;
            cp16(st + K_BYTES + r * V_ST + u * 16, V + off, ok);
        }
        cpcommit();
    };
    issue_kv(0);
    issue_kv(1);
    cpwait<1>();
    __syncthreads();

    // Q fragments (registers, whole kernel)
    uint32_t qf[4][4];
    {
        const int arow = w * 16 + (lane & 15);
        const uint32_t acol = (uint32_t)((lane >> 4) * 16);
#pragma unroll
        for (int ks = 0; ks < 4; ks++)
            ldm4(qf[ks], qb + (uint32_t)(arow * QK_ST) + ks * 32 + acol);
    }

    float acc_o[8][4];
#pragma unroll
    for (int i = 0; i < 8; i++)
#pragma unroll
        for (int q = 0; q < 4; q++) acc_o[i][q] = 0.0f;
    float rsum0 = 0.0f, rsum1 = 0.0f;

    const int row0 = mBase + w * 16 + (lane >> 2);
    const int row1 = row0 + 8;
    // x4 B addressing
    const int xrow = (lane & 7) + ((lane >> 4) << 3);
    const int xcol = ((lane >> 3) & 1) * 16;

    for (int t = 0; t < NT; t++) {
        const uint32_t st = stb + (t & 1) * STAGE;
        const int kBase = t * 128;

        // ---- score MMAs (K frags via ldm4 pairs) ----
        float acc[16][4];
#pragma unroll
        for (int i = 0; i < 16; i++)
#pragma unroll
            for (int q = 0; q < 4; q++) acc[i][q] = 0.0f;
#pragma unroll
        for (int ks = 0; ks < 4; ks++) {
#pragma unroll
            for (int n2 = 0; n2 < 8; n2++) {
                uint32_t b4[4];
                ldm4(b4, st + (uint32_t)((n2 * 16 + xrow) * QK_ST) + ks * 32 + xcol);
                mma16816(acc[n2 * 2 + 0], qf[ks], &b4[0]);
                mma16816(acc[n2 * 2 + 1], qf[ks], &b4[2]);
            }
        }

        // ---- exp + E write + rowsum + pack P fragments ----
        uint32_t eh[32];
#pragma unroll
        for (int ni = 0; ni < 16; ni++) {
            const int col0 = kBase + ni * 8 + (lane & 3) * 2;
            float e00 = 0.f, e01 = 0.f, e10 = 0.f, e11 = 0.f;
            if (col0 < S_LEN) {
                e00 = __expf(acc[ni][0]); e01 = __expf(acc[ni][1]);
                e10 = __expf(acc[ni][2]); e11 = __expf(acc[ni][3]);
            }
            const __half2 hv0 = __floats2half2_rn(e00, e01);
            const __half2 hv1 = __floats2half2_rn(e10, e11);
            eh[ni * 2]     = *(const uint32_t*)&hv0;
            eh[ni * 2 + 1] = *(const uint32_t*)&hv1;
            if (col0 < S_LEN) {
                if (row0 < S_LEN) *reinterpret_cast<__half2*>(E + (hS + row0) * S_LEN + col0) = hv0;
                if (row1 < S_LEN) *reinterpret_cast<__half2*>(E + (hS + row1) * S_LEN + col0) = hv1;
                rsum0 += __low2float(hv0) + __high2float(hv0);
                rsum1 += __low2float(hv1) + __high2float(hv1);
            }
        }

        // ---- PV MMAs (V frags via ldm4 pairs) ----
#pragma unroll
        for (int ks = 0; ks < 8; ks++) {
#pragma unroll
            for (int n2 = 0; n2 < 4; n2++) {
                uint32_t b4[4];
                ldm4(b4, st + K_BYTES + (uint32_t)((n2 * 16 + xrow) * V_ST) + ks * 32 + xcol);
                mma16816(acc_o[n2 * 2 + 0], &eh[ks * 4], &b4[0]);
                mma16816(acc_o[n2 * 2 + 1], &eh[ks * 4], &b4[2]);
            }
        }

        __syncthreads();
        if (t + 2 < NT) issue_kv(t + 2);
        if (t + 1 < NT) {
            if (t + 2 < NT) cpwait<1>(); else cpwait<0>();
            __syncthreads();
        }
    }

    // ---- finalize ----
    rsum0 += __shfl_xor_sync(0xFFFFFFFFu, rsum0, 1);
    rsum0 += __shfl_xor_sync(0xFFFFFFFFu, rsum0, 2);
    rsum1 += __shfl_xor_sync(0xFFFFFFFFu, rsum1, 1);
    rsum1 += __shfl_xor_sync(0xFFFFFFFFu, rsum1, 2);
    const float inv0 = 1.0f / rsum0;
    const float inv1 = 1.0f / rsum1;

    if (row0 < S_LEN) {
#pragma unroll
        for (int ni = 0; ni < 8; ni++) {
            const int d = ni * 8 + (lane & 3) * 2;
            *reinterpret_cast<__half2*>(AO + (long)row0 * E_DIM + h * 64 + d) =
                __floats2half2_rn(acc_o[ni][0] * inv0, acc_o[ni][1] * inv0);
        }
        if ((lane & 3) == 0) isum[hS + row0] = inv0;
    }
    if (row1 < S_LEN) {
#pragma unroll
        for (int ni = 0; ni < 8; ni++) {
            const int d = ni * 8 + (lane & 3) * 2;
            *reinterpret_cast<__half2*>(AO + (long)row1 * E_DIM + h * 64 + d) =
                __floats2half2_rn(acc_o[ni][2] * inv1, acc_o[ni][3] * inv1);
        }
        if ((lane & 3) == 0) isum[hS + row1] = inv1;
    }
}

// ---------------------------------------------------------------------------
// Small kernels
// ---------------------------------------------------------------------------
__global__ void splitH_kernel(const float* __restrict__ src, __half* __restrict__ dst, long n) {
    long i = ((long)blockIdx.x * blockDim.x + threadIdx.x) * 4;
    if (i >= n) return;
    float4 v = *(const float4*)(src + i);
    *(__half2*)(dst + i)     = __floats2half2_rn(v.x, v.y);
    *(__half2*)(dst + i + 2) = __floats2half2_rn(v.z, v.w);
}

__global__ void splitW4_kernel(const float* __restrict__ w0, const float* __restrict__ w1,
                               const float* __restrict__ w2, const float* __restrict__ w3,
                               __half* __restrict__ dstB) {
    const long nw = (long)E_DIM * E_DIM;
    const int z = blockIdx.z;
    const float* src = (z == 0) ? w0 : (z == 1) ? w1 : (z == 2) ? w2 : w3;
    __half* dst = dstB + (long)z * nw;
    long i = ((long)blockIdx.x * blockDim.x + threadIdx.x) * 4;
    if (i >= nw) return;
    float4 v = *(const float4*)(src + i);
    *(__half2*)(dst + i)     = __floats2half2_rn(v.x, v.y);
    *(__half2*)(dst + i + 2) = __floats2half2_rn(v.z, v.w);
}

__global__ void rope_split_kernel(const float* __restrict__ Q, const float* __restrict__ K,
                                  const float* __restrict__ cosp, const float* __restrict__ sinp) {
    const long total = (long)H_NUM * S_LEN * 32;
    long idx = (long)blockIdx.x * blockDim.x + threadIdx.x;
    if (idx >= total) return;
    const int d = (int)(idx & 31);
    const long hs = idx >> 5;
    const int s = (int)(hs % S_LEN);
    const long base = hs << 6;

    const float c1 = cosp[s * 64 + d], s1 = sinp[s * 64 + d];
    const float c2 = cosp[s * 64 + d + 32], s2 = sinp[s * 64 + d + 32];

    float q1 = Q[base + d], q2 = Q[base + d + 32];
    float k1 = K[base + d], k2 = K[base + d + 32];

    g_Qh[base + d]      = __float2half_rn((q1 * c1 - q2 * s1) * 0.125f);
    g_Qh[base + d + 32] = __float2half_rn((q2 * c2 + q1 * s2) * 0.125f);
    g_Kh[base + d]      = __float2half_rn(k1 * c1 - k2 * s1);
    g_Kh[base + d + 32] = __float2half_rn(k2 * c2 + k1 * s2);
}

__global__ void vtrans_kernel(const float* __restrict__ V) {
    __shared__ float tile[64][65];
    const int h = blockIdx.z;
    const int s0 = blockIdx.x * 64;
    const int t = threadIdx.x;
    for (int i = t; i < 4096; i += 256) {
        int s = i >> 6, d = i & 63;
        tile[s][d] = V[((long)h * S_LEN + s0 + s) * 64 + d];
    }
    __syncthreads();
    for (int i = t; i < 4096; i += 256) {
        int d = i >> 6, s = i & 63;
        g_Vt[((long)h * 64 + d) * S_LEN + s0 + s] = __float2half_rn(tile[s][d]);
    }
}

__global__ void normalize_kernel(float* __restrict__ W) {
    const long row = blockIdx.x;
    const float inv = g_isum[row];
    const __half* e = g_E + row * (long)S_LEN;
    float* w = W + row * (long)S_LEN;
    for (int i = threadIdx.x * 8; i < S_LEN; i += 256 * 8) {
        uint4 h4 = *(const uint4*)(e + i);
        const uint32_t hh[4] = {h4.x, h4.y, h4.z, h4.w};
        float o[8];
#pragma unroll
        for (int j = 0; j < 4; j++) {
            __half2 hb = *(const __half2*)&hh[j];
            o[j * 2 + 0] = __low2float(hb) * inv;
            o[j * 2 + 1] = __high2float(hb) * inv;
        }
        *(float4*)(w + i)     = make_float4(o[0], o[1], o[2], o[3]);
        *(float4*)(w + i + 4) = make_float4(o[4], o[5], o[6], o[7]);
    }
}

// ---------------------------------------------------------------------------
// Launch
// ---------------------------------------------------------------------------
extern "C" void kernel_launch(void* const* d_in, const int* in_sizes, int n_in,
                              void* d_out, int out_size) {
    const float* hidden = (const float*)d_in[0];
    const float* cosp   = (const float*)d_in[1];
    const float* sinp   = (const float*)d_in[2];
    const float* w[4]   = {(const float*)d_in[3], (const float*)d_in[4],
                           (const float*)d_in[5], (const float*)d_in[6]};

    float* out    = (float*)d_out;
    float* attn_w = out + (long)S_LEN * E_DIM;

    float* qkv; cudaGetSymbolAddress((void**)&qkv, g_qkv);
    __half *Hh, *Wh, *Qh, *Kh, *Vt, *E, *AO;
    float *isum;
    cudaGetSymbolAddress((void**)&Hh, g_Hh);
    cudaGetSymbolAddress((void**)&Wh, g_Wh);
    cudaGetSymbolAddress((void**)&Qh, g_Qh);    cudaGetSymbolAddress((void**)&Kh, g_Kh);
    cudaGetSymbolAddress((void**)&Vt, g_Vt);
    cudaGetSymbolAddress((void**)&E, g_E);      cudaGetSymbolAddress((void**)&AO, g_AO);
    cudaGetSymbolAddress((void**)&isum, g_isum);

    static cudaStream_t s1 = nullptr;
    static cudaEvent_t evFork = nullptr, evJoin = nullptr;
    if (!s1) {
        cudaStreamCreateWithFlags(&s1, cudaStreamNonBlocking);
        cudaEventCreateWithFlags(&evFork, cudaEventDisableTiming);
        cudaEventCreateWithFlags(&evJoin, cudaEventDisableTiming);
    }

    const int SMEM_PROJ = 2 * (128 * 80 + 128 * 80);                 // 40960
    const int SMEM_FA   = 128 * 176 + 2 * (128 * 176 + 64 * 272);    // 102400
    cudaFuncSetAttribute((const void*)mma_gemm<0>, cudaFuncAttributeMaxDynamicSharedMemorySize, SMEM_PROJ);
    cudaFuncSetAttribute((const void*)mma_gemm<1>, cudaFuncAttributeMaxDynamicSharedMemorySize, SMEM_PROJ);
    cudaFuncSetAttribute((const void*)fused_attn,  cudaFuncAttributeMaxDynamicSharedMemorySize, SMEM_FA);

    // 1) fp16 conversions
    {
        long n = (long)S_LEN * E_DIM;
        splitH_kernel<<<(int)((n / 4 + 255) / 256), 256>>>(hidden, Hh, n);
        long nw = (long)E_DIM * E_DIM;
        dim3 gw((unsigned)((nw / 4 + 255) / 256), 1, 4);
        splitW4_kernel<<<gw, 256>>>(w[0], w[1], w[2], w[3], Wh);
    }

    // 2) QKV projections (1-pass fp16), batched over z={q,k,v}
    {
        dim3 g(E_DIM / 128, (S_LEN + 127) / 128, 3);
        mma_gemm<1><<<g, 256, SMEM_PROJ>>>(Hh, E_DIM,
                                           Wh, E_DIM, (long)E_DIM * E_DIM,
                                           qkv, 0, 0, 32, S_LEN);
    }

    // 3) RoPE -> fp16 Q (scaled), K; V transpose (fp16 single)
    {
        long total = (long)H_NUM * S_LEN * 32;
        const long HSD = (long)H_NUM * S_LEN * D_DIM;
        rope_split_kernel<<<(int)((total + 255) / 256), 256>>>(qkv, qkv + HSD, cosp, sinp);
        dim3 gv(S_LEN / 64, 1, H_NUM);
        vtrans_kernel<<<gv, 256>>>(qkv + 2 * HSD);
    }

    // 4) fused attention: E (fp16) + isum + normalized AO in one kernel
    {
        dim3 g((S_LEN + 127) / 128, H_NUM);
        fused_attn<<<g, 256, SMEM_FA>>>(Qh, Kh, Vt, E, AO, isum);
    }

    // 5) FORK: normalize (attn_weights fp32) on side stream, overlapped with out-proj
    cudaEventRecord(evFork, 0);
    cudaStreamWaitEvent(s1, evFork, 0);
    normalize_kernel<<<H_NUM * S_LEN, 256, 0, s1>>>(attn_w);
    cudaEventRecord(evJoin, s1);

    // 6) out = AO Wo^T (1-pass fp16)  [main stream]
    {
        dim3 g(E_DIM / 128, (S_LEN + 127) / 128, 1);
        long nw = (long)E_DIM * E_DIM;
        mma_gemm<0><<<g, 256, SMEM_PROJ>>>(AO, E_DIM,
                                           Wh + 3 * nw, E_DIM, 0,
                                           out, E_DIM, 0, 32, S_LEN);
    }

    // 7) JOIN
    cudaStreamWaitEvent(0, evJoin, 0);
}